// round 7
// baseline (speedup 1.0000x reference)
#include <cuda_runtime.h>
#include <cuda_bf16.h>
#include <stdint.h>
#include <math.h>

#define NN_MAX 50000
#define EE_MAX 800000

// ---------------- device scratch ----------------
__device__ float  g_u[NN_MAX * 64];
__device__ float  g_v[NN_MAX * 64];
__device__ float  g_nodemax[NN_MAX * 64];
__device__ float  g_nodemin[NN_MAX * 64];
__device__ float  g_xcat[NN_MAX * 192];
__device__ float  g_h1[NN_MAX * 256];
__device__ float  g_h2[NN_MAX * 64];
__device__ float  g_h3[NN_MAX * 32];
__device__ double g_sum[256];
__device__ double g_sq[256];
__device__ float  g_Wf[256 * 64];
__device__ float  g_Wft[64 * 64];
__device__ float  g_bf[256];
__device__ float  g_saff[64], g_taff[64];
__device__ int    g_deg[NN_MAX], g_rowptr[NN_MAX + 1], g_cursor[NN_MAX], g_adj[EE_MAX];

static inline int idivup(int a, int b) { return (a + b - 1) / b; }

// packed fp32x2 FMA
__device__ __forceinline__ void ffma2(unsigned long long& acc, unsigned long long a, unsigned long long b) {
    asm("fma.rn.f32x2 %0, %1, %2, %0;" : "+l"(acc) : "l"(a), "l"(b));
}
union U64F2 { unsigned long long u; float2 f; };

#define SW128(off) ((off) ^ (((off) >> 3) & 0x70))

// warp-level bf16 MMA, m16n8k16, fp32 accumulate
__device__ __forceinline__ void mma_bf16(float* d, const uint32_t* a, uint32_t b0, uint32_t b1) {
    asm volatile(
        "mma.sync.aligned.m16n8k16.row.col.f32.bf16.bf16.f32 "
        "{%0,%1,%2,%3}, {%4,%5,%6,%7}, {%8,%9}, {%0,%1,%2,%3};"
        : "+f"(d[0]), "+f"(d[1]), "+f"(d[2]), "+f"(d[3])
        : "r"(a[0]), "r"(a[1]), "r"(a[2]), "r"(a[3]), "r"(b0), "r"(b1));
}

// ---------------- CSR build ----------------
__global__ void count_kernel(const int* __restrict__ dst, int* __restrict__ deg,
                             double* __restrict__ gsum, double* __restrict__ gsq, int E) {
    if (blockIdx.x == 0 && threadIdx.x < 256) { gsum[threadIdx.x] = 0.0; gsq[threadIdx.x] = 0.0; }
    int e = blockIdx.x * 256 + threadIdx.x;
    if (e < E) atomicAdd(&deg[dst[e]], 1);
}

__global__ void scan_kernel(const int* __restrict__ deg, int* __restrict__ rowptr,
                            int* __restrict__ cursor, int N) {
    __shared__ int warpsum[32];
    __shared__ int soff;
    int t = threadIdx.x, lane = t & 31, wid = t >> 5;
    if (t == 0) { soff = 0; rowptr[0] = 0; }
    __syncthreads();
    for (int base = 0; base < N; base += 1024) {
        int x = (base + t < N) ? deg[base + t] : 0;
        int v = x;
#pragma unroll
        for (int d = 1; d < 32; d <<= 1) {
            int y = __shfl_up_sync(0xffffffffu, v, d);
            if (lane >= d) v += y;
        }
        if (lane == 31) warpsum[wid] = v;
        __syncthreads();
        if (wid == 0) {
            int s = warpsum[lane];
#pragma unroll
            for (int d = 1; d < 32; d <<= 1) {
                int y = __shfl_up_sync(0xffffffffu, s, d);
                if (lane >= d) s += y;
            }
            warpsum[lane] = s;
        }
        __syncthreads();
        int inc = v + (wid > 0 ? warpsum[wid - 1] : 0) + soff;
        if (base + t < N) { rowptr[base + t + 1] = inc; cursor[base + t] = inc - x; }
        __syncthreads();
        if (t == 1023) soff = inc;
        __syncthreads();
    }
}

__global__ void scatter_kernel(const int* __restrict__ dst, int* __restrict__ cursor,
                               int* __restrict__ adj, int E) {
    int e = blockIdx.x * 256 + threadIdx.x;
    if (e < E) {
        int d = dst[e];
        int pos = atomicAdd(&cursor[d], 1);
        adj[pos] = e;
    }
}

// ---------------- node GEMM: u = X @ (Wtop - Wbot), v = X @ Wbot ----------------
__global__ void gemm_uv_kernel(const float* __restrict__ X, int ldx, int R, int K,
                               const float* __restrict__ Wa,
                               float* __restrict__ u, float* __restrict__ v) {
    __shared__ float Xs[64 * 32];
    __shared__ float Ws[64 * 32];
    int t = threadIdx.x;
    int tx = t & 15, ty = t >> 4;
    int r0 = blockIdx.x * 64;
    int mode = blockIdx.y;
    float* Y = mode ? v : u;
    unsigned long long acc[4][4];
#pragma unroll
    for (int i = 0; i < 4; i++)
#pragma unroll
        for (int j = 0; j < 4; j++) acc[i][j] = 0ULL;

    for (int kc = 0; kc < K; kc += 32) {
        for (int idx = t; idx < 64 * 32; idx += 256) {
            int r = idx >> 5, k = idx & 31;
            int gr = r0 + r, gk = kc + k;
            Xs[idx] = (gr < R && gk < K) ? X[(size_t)gr * ldx + gk] : 0.f;
        }
        for (int idx = t; idx < 64 * 32; idx += 256) {
            int k = idx >> 6, c = idx & 63;
            int gk = kc + k;
            float vv = 0.f;
            if (gk < K) {
                float wb = Wa[(size_t)(K + gk) * 64 + c];
                vv = mode ? wb : (Wa[(size_t)gk * 64 + c] - wb);
            }
            int chunk = ((k >> 2) + (c >> 2)) & 7;
            Ws[c * 32 + chunk * 4 + (k & 3)] = vv;
        }
        __syncthreads();
#pragma unroll
        for (int kk = 0; kk < 32; kk += 4) {
            int k4 = kk >> 2;
            ulonglong2 w[4], e[4];
#pragma unroll
            for (int j = 0; j < 4; j++) {
                int chunk = (k4 + tx) & 7;
                w[j] = *(const ulonglong2*)&Ws[(tx * 4 + j) * 32 + chunk * 4];
            }
#pragma unroll
            for (int i = 0; i < 4; i++)
                e[i] = *(const ulonglong2*)&Xs[(ty * 4 + i) * 32 + kk];
#pragma unroll
            for (int i = 0; i < 4; i++)
#pragma unroll
                for (int j = 0; j < 4; j++) {
                    ffma2(acc[i][j], e[i].x, w[j].x);
                    ffma2(acc[i][j], e[i].y, w[j].y);
                }
        }
        __syncthreads();
    }
#pragma unroll
    for (int i = 0; i < 4; i++) {
        int gr = r0 + ty * 4 + i;
        if (gr >= R) continue;
        float4 r4;
        U64F2 u0, u1, u2, u3;
        u0.u = acc[i][0]; u1.u = acc[i][1]; u2.u = acc[i][2]; u3.u = acc[i][3];
        r4.x = u0.f.x + u0.f.y; r4.y = u1.f.x + u1.f.y;
        r4.z = u2.f.x + u2.f.y; r4.w = u3.f.x + u3.f.y;
        *(float4*)&Y[(size_t)gr * 64 + tx * 4] = r4;
    }
}

// ---------------- generic GEMM for head ----------------
__global__ void gemm_kernel(const float* __restrict__ X, int ldx, int R, int K,
                            const float* __restrict__ W, int ldw, int CO,
                            const float* __restrict__ bias,
                            float* __restrict__ Y, int ldy,
                            int do_relu, int do_stats,
                            double* __restrict__ gsum, double* __restrict__ gsq) {
    __shared__ float Xs[64 * 32];
    __shared__ float Ws[64 * 32];
    __shared__ float csum[64], csq[64];
    int t = threadIdx.x;
    int tx = t & 15, ty = t >> 4;
    int r0 = blockIdx.x * 64;
    int c0 = blockIdx.y * 64;
    if (do_stats && t < 64) { csum[t] = 0.f; csq[t] = 0.f; }
    unsigned long long acc[4][4];
#pragma unroll
    for (int i = 0; i < 4; i++)
#pragma unroll
        for (int j = 0; j < 4; j++) acc[i][j] = 0ULL;

    for (int kc = 0; kc < K; kc += 32) {
        for (int idx = t; idx < 64 * 32; idx += 256) {
            int r = idx >> 5, k = idx & 31;
            int gr = r0 + r, gk = kc + k;
            Xs[idx] = (gr < R && gk < K) ? X[(size_t)gr * ldx + gk] : 0.f;
        }
        for (int idx = t; idx < 64 * 32; idx += 256) {
            int k = idx >> 6, c = idx & 63;
            int gk = kc + k, gc = c0 + c;
            float vv = (gk < K && gc < CO) ? W[(size_t)gk * ldw + gc] : 0.f;
            int chunk = ((k >> 2) + (c >> 2)) & 7;
            Ws[c * 32 + chunk * 4 + (k & 3)] = vv;
        }
        __syncthreads();
#pragma unroll
        for (int kk = 0; kk < 32; kk += 4) {
            int k4 = kk >> 2;
            ulonglong2 w[4], e[4];
#pragma unroll
            for (int j = 0; j < 4; j++) {
                int chunk = (k4 + tx) & 7;
                w[j] = *(const ulonglong2*)&Ws[(tx * 4 + j) * 32 + chunk * 4];
            }
#pragma unroll
            for (int i = 0; i < 4; i++)
                e[i] = *(const ulonglong2*)&Xs[(ty * 4 + i) * 32 + kk];
#pragma unroll
            for (int i = 0; i < 4; i++)
#pragma unroll
                for (int j = 0; j < 4; j++) {
                    ffma2(acc[i][j], e[i].x, w[j].x);
                    ffma2(acc[i][j], e[i].y, w[j].y);
                }
        }
        __syncthreads();
    }

    float ps[4] = {0.f, 0.f, 0.f, 0.f}, pq[4] = {0.f, 0.f, 0.f, 0.f};
#pragma unroll
    for (int i = 0; i < 4; i++) {
        int gr = r0 + ty * 4 + i;
        if (gr >= R) continue;
#pragma unroll
        for (int j = 0; j < 4; j++) {
            int gc = c0 + tx * 4 + j;
            if (gc >= CO) continue;
            U64F2 uu; uu.u = acc[i][j];
            float vv = uu.f.x + uu.f.y;
            if (bias) vv += bias[gc];
            if (do_relu) vv = fmaxf(vv, 0.f);
            Y[(size_t)gr * ldy + gc] = vv;
            ps[j] += vv; pq[j] += vv * vv;
        }
    }
    if (do_stats) {
        __syncthreads();
#pragma unroll
        for (int j = 0; j < 4; j++) {
            atomicAdd(&csum[tx * 4 + j], ps[j]);
            atomicAdd(&csq[tx * 4 + j], pq[j]);
        }
        __syncthreads();
        if (t < 64 && c0 + t < CO) {
            atomicAdd(&gsum[c0 + t], (double)csum[t]);
            atomicAdd(&gsq[c0 + t], (double)csq[t]);
        }
    }
}

// ---------------- edge stats pass (adj-sorted: u-rows repeat -> L1 hits) ----------------
__global__ void edge_stats_kernel(const float* __restrict__ u, const float* __restrict__ v,
                                  const int* __restrict__ src, const int* __restrict__ dst,
                                  const int* __restrict__ adj,
                                  const float* __restrict__ ba,
                                  double* __restrict__ gsum, double* __restrict__ gsq, int E) {
    __shared__ float csum[64], csq[64];
    __shared__ int sidx[256], didx[256];
    int t = threadIdx.x;
    int e0 = blockIdx.x * 256;
    int ne = min(256, E - e0);
    if (t < ne) {
        int p = adj[e0 + t];
        sidx[t] = src[p];
        didx[t] = dst[p];
    }
    if (t < 64) { csum[t] = 0.f; csq[t] = 0.f; }
    __syncthreads();
    int q = t & 15, eg = t >> 4;
    float4 b4 = *(const float4*)&ba[q * 4];
    float4 ps = {0.f, 0.f, 0.f, 0.f}, pq = {0.f, 0.f, 0.f, 0.f};
#pragma unroll 4
    for (int e = eg; e < ne; e += 16) {
        float4 u4 = *(const float4*)&u[(size_t)didx[e] * 64 + q * 4];
        float4 v4 = *(const float4*)&v[(size_t)sidx[e] * 64 + q * 4];
        float a0 = fmaxf(u4.x + v4.x + b4.x, 0.f);
        float a1 = fmaxf(u4.y + v4.y + b4.y, 0.f);
        float a2 = fmaxf(u4.z + v4.z + b4.z, 0.f);
        float a3 = fmaxf(u4.w + v4.w + b4.w, 0.f);
        ps.x += a0; pq.x += a0 * a0;
        ps.y += a1; pq.y += a1 * a1;
        ps.z += a2; pq.z += a2 * a2;
        ps.w += a3; pq.w += a3 * a3;
    }
    atomicAdd(&csum[q * 4 + 0], ps.x); atomicAdd(&csq[q * 4 + 0], pq.x);
    atomicAdd(&csum[q * 4 + 1], ps.y); atomicAdd(&csq[q * 4 + 1], pq.y);
    atomicAdd(&csum[q * 4 + 2], ps.z); atomicAdd(&csq[q * 4 + 2], pq.z);
    atomicAdd(&csum[q * 4 + 3], ps.w); atomicAdd(&csq[q * 4 + 3], pq.w);
    __syncthreads();
    if (t < 64) {
        atomicAdd(&gsum[t], (double)csum[t]);
        atomicAdd(&gsq[t], (double)csq[t]);
    }
}

// ---------------- BN fold ----------------
__global__ void fold_kernel(double* __restrict__ gsum, double* __restrict__ gsq, double count,
                            const float* __restrict__ gamma, const float* __restrict__ beta, int CH,
                            const float* __restrict__ Wn, const float* __restrict__ bn_, int COn,
                            float* __restrict__ Wf, float* __restrict__ Wft, float* __restrict__ bf,
                            float* __restrict__ saff, float* __restrict__ taff, int mode) {
    __shared__ float ss[256], tt[256];
    int t = threadIdx.x;
    if (t < CH) {
        double mu = gsum[t] / count;
        double var = gsq[t] / count - mu * mu;
        if (var < 0.0) var = 0.0;
        float sc = gamma[t] * rsqrtf((float)var + 1e-5f);
        ss[t] = sc;
        tt[t] = beta[t] - (float)mu * sc;
        gsum[t] = 0.0; gsq[t] = 0.0;
    }
    __syncthreads();
    if (mode == 1) {
        if (t < CH) { saff[t] = ss[t]; taff[t] = tt[t]; }
        return;
    }
    for (int idx = t; idx < CH * COn; idx += 256)
        Wf[idx] = ss[idx / COn] * Wn[idx];
    if (Wft) {
        for (int idx = t; idx < CH * COn; idx += 256) {
            int c = idx >> 6, k = idx & 63;
            Wft[idx] = ss[k] * Wn[k * COn + c];
        }
    }
    if (t < COn) {
        float a = bn_[t];
        for (int c = 0; c < CH; c++) a += tt[c] * Wn[c * COn + t];
        bf[t] = a;
    }
}

// ---------------- HMMA fused edge GEMM + segment max/min (persistent, A-smem reused for y2) ----------------
// dyn smem (1024-aligned): A_hi 16K | A_lo 16K | B_hi 8K | B_lo 8K ; y2s overlays A (stride 64)
#define EDGE_MMA_SMEM (49152 + 1024)
__global__ void __launch_bounds__(256, 3)
edge_gemm_agg_mma(const float* __restrict__ u, const float* __restrict__ v,
                  const int* __restrict__ src, const int* __restrict__ dst,
                  const int* __restrict__ adj,
                  const float* __restrict__ ba,
                  const float* __restrict__ Wft, const float* __restrict__ bf,
                  float* __restrict__ nodemax, float* __restrict__ nodemin,
                  double* __restrict__ gsum, double* __restrict__ gsq,
                  int E, int nTiles) {
    extern __shared__ char dynraw[];
    __shared__ int sidx[128], didx[128];
    __shared__ float bas[64], bfs[64], csum[64], csq[64];

    uintptr_t rawp = (uintptr_t)dynraw;
    char* dynp = dynraw + ((1024u - (rawp & 1023u)) & 1023u);

    char* A_hi = dynp;
    char* A_lo = dynp + 16384;
    char* B_hi = dynp + 32768;
    char* B_lo = dynp + 40960;
    float* y2s = (float*)dynp;   // overlays A_hi+A_lo after MMA (128 x 64 fp32 = 32K)

    int t = threadIdx.x;
    int wid = t >> 5, lane = t & 31;
    int grp = lane >> 2, tig = lane & 3;

    if (t < 64) { bas[t] = ba[t]; bfs[t] = bf[t]; }
    // build B_hi/B_lo from Wft [n][k] fp32, SW128-swizzled 128B rows
    for (int idx = t; idx < 64 * 64; idx += 256) {
        int n = idx >> 6, k = idx & 63;
        float w = Wft[idx];
        __nv_bfloat16 h = __float2bfloat16(w);
        __nv_bfloat16 l = __float2bfloat16(w - __bfloat162float(h));
        uint32_t off = SW128((uint32_t)(n * 128 + k * 2));
        *(unsigned short*)(B_hi + off) = __bfloat16_as_ushort(h);
        *(unsigned short*)(B_lo + off) = __bfloat16_as_ushort(l);
    }
    __syncthreads();

    for (int tile = blockIdx.x; tile < nTiles; tile += gridDim.x) {
        int e0 = tile * 128;
        int ne = min(128, E - e0);
        if (t < ne) {
            int p = adj[e0 + t];
            sidx[t] = src[p];
            didx[t] = dst[p];
        }
        if (t < 64) { csum[t] = 0.f; csq[t] = 0.f; }
        __syncthreads();
        // gather y1 = relu(u[dst]+v[src]+ba), split to bf16 hi/lo, SW128 layout
        for (int idx = t; idx < 128 * 16; idx += 256) {
            int e = idx >> 4, q = idx & 15;
            float4 y = {0.f, 0.f, 0.f, 0.f};
            if (e < ne) {
                float4 u4 = *(const float4*)&u[(size_t)didx[e] * 64 + q * 4];
                float4 v4 = *(const float4*)&v[(size_t)sidx[e] * 64 + q * 4];
                float4 b4 = *(const float4*)&bas[q * 4];
                y.x = fmaxf(u4.x + v4.x + b4.x, 0.f);
                y.y = fmaxf(u4.y + v4.y + b4.y, 0.f);
                y.z = fmaxf(u4.z + v4.z + b4.z, 0.f);
                y.w = fmaxf(u4.w + v4.w + b4.w, 0.f);
            }
            __nv_bfloat16 h0 = __float2bfloat16(y.x), h1 = __float2bfloat16(y.y);
            __nv_bfloat16 h2 = __float2bfloat16(y.z), h3 = __float2bfloat16(y.w);
            float l0f = y.x - __bfloat162float(h0), l1f = y.y - __bfloat162float(h1);
            float l2f = y.z - __bfloat162float(h2), l3f = y.w - __bfloat162float(h3);
            uint2 hp, lp;
            hp.x = (uint32_t)__bfloat16_as_ushort(h0) | ((uint32_t)__bfloat16_as_ushort(h1) << 16);
            hp.y = (uint32_t)__bfloat16_as_ushort(h2) | ((uint32_t)__bfloat16_as_ushort(h3) << 16);
            lp.x = (uint32_t)__bfloat16_as_ushort(__float2bfloat16(l0f)) |
                   ((uint32_t)__bfloat16_as_ushort(__float2bfloat16(l1f)) << 16);
            lp.y = (uint32_t)__bfloat16_as_ushort(__float2bfloat16(l2f)) |
                   ((uint32_t)__bfloat16_as_ushort(__float2bfloat16(l3f)) << 16);
            uint32_t off = SW128((uint32_t)(e * 128 + q * 8));
            *(uint2*)(A_hi + off) = hp;
            *(uint2*)(A_lo + off) = lp;
        }
        __syncthreads();

        // warp-level MMA: warp w -> rows 16w..16w+15, all 64 cols
        float acc[8][4];
#pragma unroll
        for (int j = 0; j < 8; j++)
#pragma unroll
            for (int q = 0; q < 4; q++) acc[j][q] = 0.f;

        int r0 = wid * 16 + grp;
        int r1 = r0 + 8;
#pragma unroll
        for (int ks = 0; ks < 4; ks++) {
            int c0 = ks * 32 + tig * 4;   // byte offset of k-col (bf16*2)
            int c1 = c0 + 16;             // +8 k's
            uint32_t ahi[4], alo[4];
            ahi[0] = *(const uint32_t*)(A_hi + SW128((uint32_t)(r0 * 128 + c0)));
            ahi[1] = *(const uint32_t*)(A_hi + SW128((uint32_t)(r1 * 128 + c0)));
            ahi[2] = *(const uint32_t*)(A_hi + SW128((uint32_t)(r0 * 128 + c1)));
            ahi[3] = *(const uint32_t*)(A_hi + SW128((uint32_t)(r1 * 128 + c1)));
            alo[0] = *(const uint32_t*)(A_lo + SW128((uint32_t)(r0 * 128 + c0)));
            alo[1] = *(const uint32_t*)(A_lo + SW128((uint32_t)(r1 * 128 + c0)));
            alo[2] = *(const uint32_t*)(A_lo + SW128((uint32_t)(r0 * 128 + c1)));
            alo[3] = *(const uint32_t*)(A_lo + SW128((uint32_t)(r1 * 128 + c1)));
#pragma unroll
            for (int j = 0; j < 8; j++) {
                int n0 = j * 8 + grp;
                uint32_t o0 = SW128((uint32_t)(n0 * 128 + c0));
                uint32_t o1 = SW128((uint32_t)(n0 * 128 + c1));
                uint32_t bhi0 = *(const uint32_t*)(B_hi + o0);
                uint32_t bhi1 = *(const uint32_t*)(B_hi + o1);
                uint32_t blo0 = *(const uint32_t*)(B_lo + o0);
                uint32_t blo1 = *(const uint32_t*)(B_lo + o1);
                mma_bf16(acc[j], ahi, bhi0, bhi1);
                mma_bf16(acc[j], ahi, blo0, blo1);
                mma_bf16(acc[j], alo, bhi0, bhi1);
            }
        }
        __syncthreads();   // all warps done reading A before overwrite
        // epilogue: bias + relu, write y2 into (reused) A smem, stride 64
#pragma unroll
        for (int j = 0; j < 8; j++) {
            int cc = j * 8 + tig * 2;
            float2 p0, p1;
            p0.x = fmaxf(acc[j][0] + bfs[cc + 0], 0.f);
            p0.y = fmaxf(acc[j][1] + bfs[cc + 1], 0.f);
            p1.x = fmaxf(acc[j][2] + bfs[cc + 0], 0.f);
            p1.y = fmaxf(acc[j][3] + bfs[cc + 1], 0.f);
            *(float2*)&y2s[r0 * 64 + cc] = p0;
            *(float2*)&y2s[r1 * 64 + cc] = p1;
        }
        __syncthreads();
        // stats + segment max/min over sorted-dst edges
        {
            int c = t & 63, g = t >> 6;
            int beg = g * 32, end = min(beg + 32, ne);
            float ps = 0.f, pq = 0.f;
            if (beg < end) {
                int cur = didx[beg];
                float val = y2s[beg * 64 + c];
                float mx = val, mn = val;
                ps += val; pq += val * val;
                for (int e = beg + 1; e < end; e++) {
                    int dd = didx[e];
                    val = y2s[e * 64 + c];
                    ps += val; pq += val * val;
                    if (dd != cur) {
                        atomicMax((unsigned int*)&nodemax[(size_t)cur * 64 + c], __float_as_uint(mx));
                        atomicMin((unsigned int*)&nodemin[(size_t)cur * 64 + c], __float_as_uint(mn));
                        cur = dd; mx = val; mn = val;
                    } else {
                        mx = fmaxf(mx, val); mn = fminf(mn, val);
                    }
                }
                atomicMax((unsigned int*)&nodemax[(size_t)cur * 64 + c], __float_as_uint(mx));
                atomicMin((unsigned int*)&nodemin[(size_t)cur * 64 + c], __float_as_uint(mn));
            }
            atomicAdd(&csum[c], ps);
            atomicAdd(&csq[c], pq);
        }
        __syncthreads();
        if (t < 64) {
            atomicAdd(&gsum[t], (double)csum[t]);
            atomicAdd(&gsq[t], (double)csq[t]);
        }
        __syncthreads();
    }
}

// ---------------- finalize: xcat column block = affine(max/min), zero-fill ----------------
__global__ void finalize_kernel(const float* __restrict__ nodemax, const float* __restrict__ nodemin,
                                const int* __restrict__ deg,
                                const float* __restrict__ s, const float* __restrict__ tt,
                                float* __restrict__ xcat, int col_off, int N) {
    int idx = blockIdx.x * 256 + threadIdx.x;
    int n = idx >> 4, q = idx & 15;
    if (n >= N) return;
    float4 mx = *(const float4*)&nodemax[(size_t)n * 64 + q * 4];
    float4 mn = *(const float4*)&nodemin[(size_t)n * 64 + q * 4];
    float4 s4 = *(const float4*)&s[q * 4];
    float4 t4 = *(const float4*)&tt[q * 4];
    float4 r = {0.f, 0.f, 0.f, 0.f};
    if (deg[n] > 0) {
        r.x = s4.x * (s4.x >= 0.f ? mx.x : mn.x) + t4.x;
        r.y = s4.y * (s4.y >= 0.f ? mx.y : mn.y) + t4.y;
        r.z = s4.z * (s4.z >= 0.f ? mx.z : mn.z) + t4.z;
        r.w = s4.w * (s4.w >= 0.f ? mx.w : mn.w) + t4.w;
    }
    *(float4*)&xcat[(size_t)n * 192 + col_off + q * 4] = r;
}

// ---------------- final: logits + log_softmax ----------------
__global__ void final_kernel(const float* __restrict__ h3, const float* __restrict__ Wf,
                             const float* __restrict__ bf, float* __restrict__ out, int N) {
    __shared__ float Ws[32 * 24];
    __shared__ float bs[24];
    __shared__ float hs[256 * 33];
    int t = threadIdx.x;
    for (int idx = t; idx < 32 * 24; idx += 256) Ws[idx] = Wf[idx];
    if (t < 24) bs[t] = bf[t];
    int n0 = blockIdx.x * 256;
    int cnt = min(256, N - n0);
    for (int idx = t; idx < cnt * 32; idx += 256) {
        int n = idx >> 5, c = idx & 31;
        hs[n * 33 + c] = h3[(size_t)(n0 + n) * 32 + c];
    }
    __syncthreads();
    float l[24];
    if (t < cnt) {
        float m = -3.4e38f;
#pragma unroll
        for (int j = 0; j < 24; j++) {
            float a = bs[j];
#pragma unroll
            for (int k = 0; k < 32; k++) a += hs[t * 33 + k] * Ws[k * 24 + j];
            l[j] = a;
            m = fmaxf(m, a);
        }
        float sum = 0.f;
#pragma unroll
        for (int j = 0; j < 24; j++) sum += __expf(l[j] - m);
        float lse = m + __logf(sum);
#pragma unroll
        for (int j = 0; j < 24; j++) l[j] -= lse;
    }
    __syncthreads();
    if (t < cnt) {
#pragma unroll
        for (int j = 0; j < 24; j++) hs[t * 33 + j] = l[j];
    }
    __syncthreads();
    for (int idx = t; idx < cnt * 24; idx += 256) {
        int n = idx / 24, j = idx % 24;
        out[(size_t)(n0 + n) * 24 + j] = hs[n * 33 + j];
    }
}

// ---------------- host orchestration ----------------
extern "C" void kernel_launch(void* const* d_in, const int* in_sizes, int n_in,
                              void* d_out, int out_size) {
    const float* x    = (const float*)d_in[0];
    const float* W1a  = (const float*)d_in[1];
    const float* b1a  = (const float*)d_in[2];
    const float* g1a  = (const float*)d_in[3];
    const float* be1a = (const float*)d_in[4];
    const float* W1b  = (const float*)d_in[5];
    const float* b1b  = (const float*)d_in[6];
    const float* g1b  = (const float*)d_in[7];
    const float* be1b = (const float*)d_in[8];
    const float* Wa   = (const float*)d_in[9];
    const float* ba   = (const float*)d_in[10];
    const float* ga   = (const float*)d_in[11];
    const float* bea  = (const float*)d_in[12];
    const float* Wb   = (const float*)d_in[13];
    const float* bb   = (const float*)d_in[14];
    const float* gb   = (const float*)d_in[15];
    const float* beb  = (const float*)d_in[16];
    const float* Wl   = (const float*)d_in[17];
    const float* bl   = (const float*)d_in[18];
    const float* gl   = (const float*)d_in[19];
    const float* bel  = (const float*)d_in[20];
    const float* Wm1  = (const float*)d_in[21];
    const float* bm1  = (const float*)d_in[22];
    const float* gm1  = (const float*)d_in[23];
    const float* bem1 = (const float*)d_in[24];
    const float* Wm2  = (const float*)d_in[25];
    const float* bm2  = (const float*)d_in[26];
    const float* gm2  = (const float*)d_in[27];
    const float* bem2 = (const float*)d_in[28];
    const float* Wo   = (const float*)d_in[29];
    const float* bo   = (const float*)d_in[30];
    const int*   eidx = (const int*)d_in[31];

    int N = in_sizes[0] / 6;
    int E = in_sizes[31] / 2;
    const int* src = eidx;
    const int* dst = eidx + E;

    float *u, *v, *nodemax, *nodemin, *xcat, *h1, *h2, *h3, *Wf, *Wft, *bf, *saff, *taff;
    double *gsum, *gsq;
    int *deg, *rowptr, *cursor, *adj;
    cudaGetSymbolAddress((void**)&u, g_u);
    cudaGetSymbolAddress((void**)&v, g_v);
    cudaGetSymbolAddress((void**)&nodemax, g_nodemax);
    cudaGetSymbolAddress((void**)&nodemin, g_nodemin);
    cudaGetSymbolAddress((void**)&xcat, g_xcat);
    cudaGetSymbolAddress((void**)&h1, g_h1);
    cudaGetSymbolAddress((void**)&h2, g_h2);
    cudaGetSymbolAddress((void**)&h3, g_h3);
    cudaGetSymbolAddress((void**)&Wf, g_Wf);
    cudaGetSymbolAddress((void**)&Wft, g_Wft);
    cudaGetSymbolAddress((void**)&bf, g_bf);
    cudaGetSymbolAddress((void**)&saff, g_saff);
    cudaGetSymbolAddress((void**)&taff, g_taff);
    cudaGetSymbolAddress((void**)&gsum, g_sum);
    cudaGetSymbolAddress((void**)&gsq, g_sq);
    cudaGetSymbolAddress((void**)&deg, g_deg);
    cudaGetSymbolAddress((void**)&rowptr, g_rowptr);
    cudaGetSymbolAddress((void**)&cursor, g_cursor);
    cudaGetSymbolAddress((void**)&adj, g_adj);

    cudaFuncSetAttribute(edge_gemm_agg_mma, cudaFuncAttributeMaxDynamicSharedMemorySize, EDGE_MMA_SMEM);

    cudaMemsetAsync(deg, 0, N * sizeof(int));
    cudaMemsetAsync(nodemax, 0, (size_t)N * 64 * sizeof(float));
    cudaMemsetAsync(nodemin, 0x7F, (size_t)N * 64 * sizeof(float));

    count_kernel<<<idivup(E, 256), 256>>>(dst, deg, gsum, gsq, E);
    scan_kernel<<<1, 1024>>>(deg, rowptr, cursor, N);
    scatter_kernel<<<idivup(E, 256), 256>>>(dst, cursor, adj, E);

    struct ConvP {
        const float* xin; int ldx; int K;
        const float *Wa_, *ba_, *ga_, *bea_, *Wb_, *bb_, *gb_, *beb_;
    };
    ConvP convs[3] = {
        { x,         6,   6,  W1a,           b1a,     g1a,     be1a,     W1b,          b1b,     g1b,     be1b     },
        { xcat,      192, 64, Wa,            ba,      ga,      bea,      Wb,           bb,      gb,      beb      },
        { xcat + 64, 192, 64, Wa + 128 * 64, ba + 64, ga + 64, bea + 64, Wb + 64 * 64, bb + 64, gb + 64, beb + 64 },
    };

    int nTiles = idivup(E, 128);
    for (int cv = 0; cv < 3; cv++) {
        const ConvP& P = convs[cv];
        if (cv > 0) {
            cudaMemsetAsync(nodemax, 0, (size_t)N * 64 * sizeof(float));
            cudaMemsetAsync(nodemin, 0x7F, (size_t)N * 64 * sizeof(float));
        }
        gemm_uv_kernel<<<dim3(idivup(N, 64), 2), 256>>>(P.xin, P.ldx, N, P.K, P.Wa_, u, v);
        edge_stats_kernel<<<idivup(E, 256), 256>>>(u, v, src, dst, adj, P.ba_, gsum, gsq, E);
        fold_kernel<<<1, 256>>>(gsum, gsq, (double)E, P.ga_, P.bea_, 64,
                                P.Wb_, P.bb_, 64, Wf, Wft, bf, (float*)0, (float*)0, 0);
        edge_gemm_agg_mma<<<592, 256, EDGE_MMA_SMEM>>>(u, v, src, dst, adj, P.ba_,
                                                       Wft, bf, nodemax, nodemin,
                                                       gsum, gsq, E, nTiles);
        fold_kernel<<<1, 256>>>(gsum, gsq, (double)E, P.gb_, P.beb_, 64,
                                (const float*)0, (const float*)0, 0, (float*)0, (float*)0, (float*)0,
                                saff, taff, 1);
        finalize_kernel<<<idivup(N * 16, 256), 256>>>(nodemax, nodemin, deg, saff, taff,
                                                      xcat, cv * 64, N);
    }

    gemm_kernel<<<dim3(idivup(N, 64), 4), 256>>>(xcat, 192, N, 192, Wl, 256, 256, bl,
                                                 h1, 256, 1, 1, gsum, gsq);
    fold_kernel<<<1, 256>>>(gsum, gsq, (double)N, gl, bel, 256, Wm1, bm1, 64, Wf, (float*)0, bf,
                            (float*)0, (float*)0, 0);
    gemm_kernel<<<dim3(idivup(N, 64), 1), 256>>>(h1, 256, N, 256, Wf, 64, 64, bf,
                                                 h2, 64, 1, 1, gsum, gsq);
    fold_kernel<<<1, 256>>>(gsum, gsq, (double)N, gm1, bem1, 64, Wm2, bm2, 32, Wf, (float*)0, bf,
                            (float*)0, (float*)0, 0);
    gemm_kernel<<<dim3(idivup(N, 64), 1), 256>>>(h2, 64, N, 64, Wf, 32, 32, bf,
                                                 h3, 32, 1, 1, gsum, gsq);
    fold_kernel<<<1, 256>>>(gsum, gsq, (double)N, gm2, bem2, 32, Wo, bo, 24, Wf, (float*)0, bf,
                            (float*)0, (float*)0, 0);
    final_kernel<<<idivup(N, 256), 256>>>(h3, Wf, bf, (float*)d_out, N);
}

// round 8
// speedup vs baseline: 1.0855x; 1.0855x over previous
#include <cuda_runtime.h>
#include <cuda_bf16.h>
#include <stdint.h>
#include <math.h>

#define NN_MAX 50000
#define EE_MAX 800000

// ---------------- device scratch ----------------
__device__ float  g_u[NN_MAX * 64];
__device__ float  g_v[NN_MAX * 64];
__device__ float  g_nodemax[NN_MAX * 64];
__device__ float  g_nodemin[NN_MAX * 64];
__device__ float  g_xcat[NN_MAX * 192];
__device__ float  g_h1[NN_MAX * 256];
__device__ float  g_h2[NN_MAX * 64];
__device__ float  g_h3[NN_MAX * 32];
__device__ double g_sum[256];
__device__ double g_sq[256];
__device__ float  g_Wf[256 * 64];
__device__ float  g_Wft[64 * 64];
__device__ float  g_bf[256];
__device__ float  g_saff[64], g_taff[64];
__device__ int    g_deg[NN_MAX], g_rowptr[NN_MAX + 1], g_cursor[NN_MAX];
__device__ int    g_adj_src[EE_MAX], g_adj_dst[EE_MAX];

static inline int idivup(int a, int b) { return (a + b - 1) / b; }

// packed fp32x2 FMA
__device__ __forceinline__ void ffma2(unsigned long long& acc, unsigned long long a, unsigned long long b) {
    asm("fma.rn.f32x2 %0, %1, %2, %0;" : "+l"(acc) : "l"(a), "l"(b));
}
union U64F2 { unsigned long long u; float2 f; };

#define SW128(off) ((off) ^ (((off) >> 3) & 0x70))

// warp-level bf16 MMA, m16n8k16, fp32 accumulate
__device__ __forceinline__ void mma_bf16(float* d, const uint32_t* a, uint32_t b0, uint32_t b1) {
    asm volatile(
        "mma.sync.aligned.m16n8k16.row.col.f32.bf16.bf16.f32 "
        "{%0,%1,%2,%3}, {%4,%5,%6,%7}, {%8,%9}, {%0,%1,%2,%3};"
        : "+f"(d[0]), "+f"(d[1]), "+f"(d[2]), "+f"(d[3])
        : "r"(a[0]), "r"(a[1]), "r"(a[2]), "r"(a[3]), "r"(b0), "r"(b1));
}

// ---------------- CSR build ----------------
__global__ void count_kernel(const int* __restrict__ dst, int* __restrict__ deg,
                             double* __restrict__ gsum, double* __restrict__ gsq, int E) {
    if (blockIdx.x == 0 && threadIdx.x < 256) { gsum[threadIdx.x] = 0.0; gsq[threadIdx.x] = 0.0; }
    int e = blockIdx.x * 256 + threadIdx.x;
    if (e < E) atomicAdd(&deg[dst[e]], 1);
}

__global__ void scan_kernel(const int* __restrict__ deg, int* __restrict__ rowptr,
                            int* __restrict__ cursor, int N) {
    __shared__ int warpsum[32];
    __shared__ int soff;
    int t = threadIdx.x, lane = t & 31, wid = t >> 5;
    if (t == 0) { soff = 0; rowptr[0] = 0; }
    __syncthreads();
    for (int base = 0; base < N; base += 1024) {
        int x = (base + t < N) ? deg[base + t] : 0;
        int v = x;
#pragma unroll
        for (int d = 1; d < 32; d <<= 1) {
            int y = __shfl_up_sync(0xffffffffu, v, d);
            if (lane >= d) v += y;
        }
        if (lane == 31) warpsum[wid] = v;
        __syncthreads();
        if (wid == 0) {
            int s = warpsum[lane];
#pragma unroll
            for (int d = 1; d < 32; d <<= 1) {
                int y = __shfl_up_sync(0xffffffffu, s, d);
                if (lane >= d) s += y;
            }
            warpsum[lane] = s;
        }
        __syncthreads();
        int inc = v + (wid > 0 ? warpsum[wid - 1] : 0) + soff;
        if (base + t < N) { rowptr[base + t + 1] = inc; cursor[base + t] = inc - x; }
        __syncthreads();
        if (t == 1023) soff = inc;
        __syncthreads();
    }
}

// scatter sorted src/dst VALUES (not edge ids) -> later passes read them linearly
__global__ void scatter_kernel(const int* __restrict__ src, const int* __restrict__ dst,
                               int* __restrict__ cursor,
                               int* __restrict__ adj_src, int* __restrict__ adj_dst, int E) {
    int e = blockIdx.x * 256 + threadIdx.x;
    if (e < E) {
        int d = dst[e];
        int pos = atomicAdd(&cursor[d], 1);
        adj_src[pos] = src[e];
        adj_dst[pos] = d;
    }
}

// ---------------- node GEMM: u = X @ (Wtop - Wbot), v = X @ Wbot ----------------
__global__ void gemm_uv_kernel(const float* __restrict__ X, int ldx, int R, int K,
                               const float* __restrict__ Wa,
                               float* __restrict__ u, float* __restrict__ v) {
    __shared__ float Xs[64 * 32];
    __shared__ float Ws[64 * 32];
    int t = threadIdx.x;
    int tx = t & 15, ty = t >> 4;
    int r0 = blockIdx.x * 64;
    int mode = blockIdx.y;
    float* Y = mode ? v : u;
    unsigned long long acc[4][4];
#pragma unroll
    for (int i = 0; i < 4; i++)
#pragma unroll
        for (int j = 0; j < 4; j++) acc[i][j] = 0ULL;

    for (int kc = 0; kc < K; kc += 32) {
        for (int idx = t; idx < 64 * 32; idx += 256) {
            int r = idx >> 5, k = idx & 31;
            int gr = r0 + r, gk = kc + k;
            Xs[idx] = (gr < R && gk < K) ? X[(size_t)gr * ldx + gk] : 0.f;
        }
        for (int idx = t; idx < 64 * 32; idx += 256) {
            int k = idx >> 6, c = idx & 63;
            int gk = kc + k;
            float vv = 0.f;
            if (gk < K) {
                float wb = Wa[(size_t)(K + gk) * 64 + c];
                vv = mode ? wb : (Wa[(size_t)gk * 64 + c] - wb);
            }
            int chunk = ((k >> 2) + (c >> 2)) & 7;
            Ws[c * 32 + chunk * 4 + (k & 3)] = vv;
        }
        __syncthreads();
#pragma unroll
        for (int kk = 0; kk < 32; kk += 4) {
            int k4 = kk >> 2;
            ulonglong2 w[4], e[4];
#pragma unroll
            for (int j = 0; j < 4; j++) {
                int chunk = (k4 + tx) & 7;
                w[j] = *(const ulonglong2*)&Ws[(tx * 4 + j) * 32 + chunk * 4];
            }
#pragma unroll
            for (int i = 0; i < 4; i++)
                e[i] = *(const ulonglong2*)&Xs[(ty * 4 + i) * 32 + kk];
#pragma unroll
            for (int i = 0; i < 4; i++)
#pragma unroll
                for (int j = 0; j < 4; j++) {
                    ffma2(acc[i][j], e[i].x, w[j].x);
                    ffma2(acc[i][j], e[i].y, w[j].y);
                }
        }
        __syncthreads();
    }
#pragma unroll
    for (int i = 0; i < 4; i++) {
        int gr = r0 + ty * 4 + i;
        if (gr >= R) continue;
        float4 r4;
        U64F2 u0, u1, u2, u3;
        u0.u = acc[i][0]; u1.u = acc[i][1]; u2.u = acc[i][2]; u3.u = acc[i][3];
        r4.x = u0.f.x + u0.f.y; r4.y = u1.f.x + u1.f.y;
        r4.z = u2.f.x + u2.f.y; r4.w = u3.f.x + u3.f.y;
        *(float4*)&Y[(size_t)gr * 64 + tx * 4] = r4;
    }
}

// ---------------- generic GEMM for head ----------------
__global__ void gemm_kernel(const float* __restrict__ X, int ldx, int R, int K,
                            const float* __restrict__ W, int ldw, int CO,
                            const float* __restrict__ bias,
                            float* __restrict__ Y, int ldy,
                            int do_relu, int do_stats,
                            double* __restrict__ gsum, double* __restrict__ gsq) {
    __shared__ float Xs[64 * 32];
    __shared__ float Ws[64 * 32];
    __shared__ float csum[64], csq[64];
    int t = threadIdx.x;
    int tx = t & 15, ty = t >> 4;
    int r0 = blockIdx.x * 64;
    int c0 = blockIdx.y * 64;
    if (do_stats && t < 64) { csum[t] = 0.f; csq[t] = 0.f; }
    unsigned long long acc[4][4];
#pragma unroll
    for (int i = 0; i < 4; i++)
#pragma unroll
        for (int j = 0; j < 4; j++) acc[i][j] = 0ULL;

    for (int kc = 0; kc < K; kc += 32) {
        for (int idx = t; idx < 64 * 32; idx += 256) {
            int r = idx >> 5, k = idx & 31;
            int gr = r0 + r, gk = kc + k;
            Xs[idx] = (gr < R && gk < K) ? X[(size_t)gr * ldx + gk] : 0.f;
        }
        for (int idx = t; idx < 64 * 32; idx += 256) {
            int k = idx >> 6, c = idx & 63;
            int gk = kc + k, gc = c0 + c;
            float vv = (gk < K && gc < CO) ? W[(size_t)gk * ldw + gc] : 0.f;
            int chunk = ((k >> 2) + (c >> 2)) & 7;
            Ws[c * 32 + chunk * 4 + (k & 3)] = vv;
        }
        __syncthreads();
#pragma unroll
        for (int kk = 0; kk < 32; kk += 4) {
            int k4 = kk >> 2;
            ulonglong2 w[4], e[4];
#pragma unroll
            for (int j = 0; j < 4; j++) {
                int chunk = (k4 + tx) & 7;
                w[j] = *(const ulonglong2*)&Ws[(tx * 4 + j) * 32 + chunk * 4];
            }
#pragma unroll
            for (int i = 0; i < 4; i++)
                e[i] = *(const ulonglong2*)&Xs[(ty * 4 + i) * 32 + kk];
#pragma unroll
            for (int i = 0; i < 4; i++)
#pragma unroll
                for (int j = 0; j < 4; j++) {
                    ffma2(acc[i][j], e[i].x, w[j].x);
                    ffma2(acc[i][j], e[i].y, w[j].y);
                }
        }
        __syncthreads();
    }

    float ps[4] = {0.f, 0.f, 0.f, 0.f}, pq[4] = {0.f, 0.f, 0.f, 0.f};
#pragma unroll
    for (int i = 0; i < 4; i++) {
        int gr = r0 + ty * 4 + i;
        if (gr >= R) continue;
#pragma unroll
        for (int j = 0; j < 4; j++) {
            int gc = c0 + tx * 4 + j;
            if (gc >= CO) continue;
            U64F2 uu; uu.u = acc[i][j];
            float vv = uu.f.x + uu.f.y;
            if (bias) vv += bias[gc];
            if (do_relu) vv = fmaxf(vv, 0.f);
            Y[(size_t)gr * ldy + gc] = vv;
            ps[j] += vv; pq[j] += vv * vv;
        }
    }
    if (do_stats) {
        __syncthreads();
#pragma unroll
        for (int j = 0; j < 4; j++) {
            atomicAdd(&csum[tx * 4 + j], ps[j]);
            atomicAdd(&csq[tx * 4 + j], pq[j]);
        }
        __syncthreads();
        if (t < 64 && c0 + t < CO) {
            atomicAdd(&gsum[c0 + t], (double)csum[t]);
            atomicAdd(&gsq[c0 + t], (double)csq[t]);
        }
    }
}

// ---------------- edge stats pass (sorted, linear index reads) ----------------
__global__ void edge_stats_kernel(const float* __restrict__ u, const float* __restrict__ v,
                                  const int* __restrict__ adj_src, const int* __restrict__ adj_dst,
                                  const float* __restrict__ ba,
                                  double* __restrict__ gsum, double* __restrict__ gsq, int E) {
    __shared__ float csum[64], csq[64];
    __shared__ int sidx[256], didx[256];
    int t = threadIdx.x;
    int e0 = blockIdx.x * 256;
    int ne = min(256, E - e0);
    if (t < ne) { sidx[t] = adj_src[e0 + t]; didx[t] = adj_dst[e0 + t]; }
    if (t < 64) { csum[t] = 0.f; csq[t] = 0.f; }
    __syncthreads();
    int q = t & 15, eg = t >> 4;
    float4 b4 = *(const float4*)&ba[q * 4];
    float4 ps = {0.f, 0.f, 0.f, 0.f}, pq = {0.f, 0.f, 0.f, 0.f};
    for (int e = eg; e < ne; e += 16) {
        float4 u4 = *(const float4*)&u[(size_t)didx[e] * 64 + q * 4];
        float4 v4 = *(const float4*)&v[(size_t)sidx[e] * 64 + q * 4];
        float a0 = fmaxf(u4.x + v4.x + b4.x, 0.f);
        float a1 = fmaxf(u4.y + v4.y + b4.y, 0.f);
        float a2 = fmaxf(u4.z + v4.z + b4.z, 0.f);
        float a3 = fmaxf(u4.w + v4.w + b4.w, 0.f);
        ps.x += a0; pq.x += a0 * a0;
        ps.y += a1; pq.y += a1 * a1;
        ps.z += a2; pq.z += a2 * a2;
        ps.w += a3; pq.w += a3 * a3;
    }
    atomicAdd(&csum[q * 4 + 0], ps.x); atomicAdd(&csq[q * 4 + 0], pq.x);
    atomicAdd(&csum[q * 4 + 1], ps.y); atomicAdd(&csq[q * 4 + 1], pq.y);
    atomicAdd(&csum[q * 4 + 2], ps.z); atomicAdd(&csq[q * 4 + 2], pq.z);
    atomicAdd(&csum[q * 4 + 3], ps.w); atomicAdd(&csq[q * 4 + 3], pq.w);
    __syncthreads();
    if (t < 64) {
        atomicAdd(&gsum[t], (double)csum[t]);
        atomicAdd(&gsq[t], (double)csq[t]);
    }
}

// ---------------- BN fold ----------------
__global__ void fold_kernel(double* __restrict__ gsum, double* __restrict__ gsq, double count,
                            const float* __restrict__ gamma, const float* __restrict__ beta, int CH,
                            const float* __restrict__ Wn, const float* __restrict__ bn_, int COn,
                            float* __restrict__ Wf, float* __restrict__ Wft, float* __restrict__ bf,
                            float* __restrict__ saff, float* __restrict__ taff, int mode) {
    __shared__ float ss[256], tt[256];
    int t = threadIdx.x;
    if (t < CH) {
        double mu = gsum[t] / count;
        double var = gsq[t] / count - mu * mu;
        if (var < 0.0) var = 0.0;
        float sc = gamma[t] * rsqrtf((float)var + 1e-5f);
        ss[t] = sc;
        tt[t] = beta[t] - (float)mu * sc;
        gsum[t] = 0.0; gsq[t] = 0.0;
    }
    __syncthreads();
    if (mode == 1) {
        if (t < CH) { saff[t] = ss[t]; taff[t] = tt[t]; }
        return;
    }
    for (int idx = t; idx < CH * COn; idx += 256)
        Wf[idx] = ss[idx / COn] * Wn[idx];
    if (Wft) {
        for (int idx = t; idx < CH * COn; idx += 256) {
            int c = idx >> 6, k = idx & 63;
            Wft[idx] = ss[k] * Wn[k * COn + c];
        }
    }
    if (t < COn) {
        float a = bn_[t];
        for (int c = 0; c < CH; c++) a += tt[c] * Wn[c * COn + t];
        bf[t] = a;
    }
}

// ---------------- HMMA fused edge GEMM + segment max/min (persistent) ----------------
// dyn smem (1024-aligned): A_hi 16K | A_lo 16K | B_hi 8K | B_lo 8K | y2s 128*68*4
#define EDGE_MMA_SMEM (83968 + 1024)
__global__ void __launch_bounds__(256, 2)
edge_gemm_agg_mma(const float* __restrict__ u, const float* __restrict__ v,
                  const int* __restrict__ adj_src, const int* __restrict__ adj_dst,
                  const float* __restrict__ ba,
                  const float* __restrict__ Wft, const float* __restrict__ bf,
                  float* __restrict__ nodemax, float* __restrict__ nodemin,
                  double* __restrict__ gsum, double* __restrict__ gsq,
                  int E, int nTiles) {
    extern __shared__ char dynraw[];
    __shared__ int sidx[128], didx[128];
    __shared__ float bas[64], bfs[64], csum[64], csq[64];

    uintptr_t rawp = (uintptr_t)dynraw;
    char* dynp = dynraw + ((1024u - (rawp & 1023u)) & 1023u);

    char* A_hi = dynp;
    char* A_lo = dynp + 16384;
    char* B_hi = dynp + 32768;
    char* B_lo = dynp + 40960;
    float* y2s = (float*)(dynp + 49152);   // [128][68]

    int t = threadIdx.x;
    int wid = t >> 5, lane = t & 31;
    int grp = lane >> 2, tig = lane & 3;

    if (t < 64) { bas[t] = ba[t]; bfs[t] = bf[t]; }
    // build B_hi/B_lo from Wft [n][k] fp32, SW128-swizzled 128B rows
    for (int idx = t; idx < 64 * 64; idx += 256) {
        int n = idx >> 6, k = idx & 63;
        float w = Wft[idx];
        __nv_bfloat16 h = __float2bfloat16(w);
        __nv_bfloat16 l = __float2bfloat16(w - __bfloat162float(h));
        uint32_t off = SW128((uint32_t)(n * 128 + k * 2));
        *(unsigned short*)(B_hi + off) = __bfloat16_as_ushort(h);
        *(unsigned short*)(B_lo + off) = __bfloat16_as_ushort(l);
    }
    __syncthreads();

    for (int tile = blockIdx.x; tile < nTiles; tile += gridDim.x) {
        int e0 = tile * 128;
        int ne = min(128, E - e0);
        if (t < ne) {
            sidx[t] = adj_src[e0 + t];
            didx[t] = adj_dst[e0 + t];
        }
        if (t < 64) { csum[t] = 0.f; csq[t] = 0.f; }
        __syncthreads();
        // gather y1 = relu(u[dst]+v[src]+ba), split to bf16 hi/lo, SW128 layout
        for (int idx = t; idx < 128 * 16; idx += 256) {
            int e = idx >> 4, q = idx & 15;
            float4 y = {0.f, 0.f, 0.f, 0.f};
            if (e < ne) {
                float4 u4 = *(const float4*)&u[(size_t)didx[e] * 64 + q * 4];
                float4 v4 = *(const float4*)&v[(size_t)sidx[e] * 64 + q * 4];
                float4 b4 = *(const float4*)&bas[q * 4];
                y.x = fmaxf(u4.x + v4.x + b4.x, 0.f);
                y.y = fmaxf(u4.y + v4.y + b4.y, 0.f);
                y.z = fmaxf(u4.z + v4.z + b4.z, 0.f);
                y.w = fmaxf(u4.w + v4.w + b4.w, 0.f);
            }
            __nv_bfloat16 h0 = __float2bfloat16(y.x), h1 = __float2bfloat16(y.y);
            __nv_bfloat16 h2 = __float2bfloat16(y.z), h3 = __float2bfloat16(y.w);
            float l0f = y.x - __bfloat162float(h0), l1f = y.y - __bfloat162float(h1);
            float l2f = y.z - __bfloat162float(h2), l3f = y.w - __bfloat162float(h3);
            uint2 hp, lp;
            hp.x = (uint32_t)__bfloat16_as_ushort(h0) | ((uint32_t)__bfloat16_as_ushort(h1) << 16);
            hp.y = (uint32_t)__bfloat16_as_ushort(h2) | ((uint32_t)__bfloat16_as_ushort(h3) << 16);
            lp.x = (uint32_t)__bfloat16_as_ushort(__float2bfloat16(l0f)) |
                   ((uint32_t)__bfloat16_as_ushort(__float2bfloat16(l1f)) << 16);
            lp.y = (uint32_t)__bfloat16_as_ushort(__float2bfloat16(l2f)) |
                   ((uint32_t)__bfloat16_as_ushort(__float2bfloat16(l3f)) << 16);
            uint32_t off = SW128((uint32_t)(e * 128 + q * 8));
            *(uint2*)(A_hi + off) = hp;
            *(uint2*)(A_lo + off) = lp;
        }
        __syncthreads();

        // warp-level MMA: warp w -> rows 16w..16w+15, all 64 cols
        float acc[8][4];
#pragma unroll
        for (int j = 0; j < 8; j++)
#pragma unroll
            for (int q = 0; q < 4; q++) acc[j][q] = 0.f;

        int r0 = wid * 16 + grp;
        int r1 = r0 + 8;
#pragma unroll
        for (int ks = 0; ks < 4; ks++) {
            int c0 = ks * 32 + tig * 4;   // byte offset of k-col (bf16*2)
            int c1 = c0 + 16;             // +8 k's
            uint32_t ahi[4], alo[4];
            ahi[0] = *(const uint32_t*)(A_hi + SW128((uint32_t)(r0 * 128 + c0)));
            ahi[1] = *(const uint32_t*)(A_hi + SW128((uint32_t)(r1 * 128 + c0)));
            ahi[2] = *(const uint32_t*)(A_hi + SW128((uint32_t)(r0 * 128 + c1)));
            ahi[3] = *(const uint32_t*)(A_hi + SW128((uint32_t)(r1 * 128 + c1)));
            alo[0] = *(const uint32_t*)(A_lo + SW128((uint32_t)(r0 * 128 + c0)));
            alo[1] = *(const uint32_t*)(A_lo + SW128((uint32_t)(r1 * 128 + c0)));
            alo[2] = *(const uint32_t*)(A_lo + SW128((uint32_t)(r0 * 128 + c1)));
            alo[3] = *(const uint32_t*)(A_lo + SW128((uint32_t)(r1 * 128 + c1)));
#pragma unroll
            for (int j = 0; j < 8; j++) {
                int n0 = j * 8 + grp;
                uint32_t o0 = SW128((uint32_t)(n0 * 128 + c0));
                uint32_t o1 = SW128((uint32_t)(n0 * 128 + c1));
                uint32_t bhi0 = *(const uint32_t*)(B_hi + o0);
                uint32_t bhi1 = *(const uint32_t*)(B_hi + o1);
                uint32_t blo0 = *(const uint32_t*)(B_lo + o0);
                uint32_t blo1 = *(const uint32_t*)(B_lo + o1);
                mma_bf16(acc[j], ahi, bhi0, bhi1);
                mma_bf16(acc[j], ahi, blo0, blo1);
                mma_bf16(acc[j], alo, bhi0, bhi1);
            }
        }
        // epilogue: bias + relu, write to y2s (stride 68 -> conflict-free)
#pragma unroll
        for (int j = 0; j < 8; j++) {
            int cc = j * 8 + tig * 2;
            float2 p0, p1;
            p0.x = fmaxf(acc[j][0] + bfs[cc + 0], 0.f);
            p0.y = fmaxf(acc[j][1] + bfs[cc + 1], 0.f);
            p1.x = fmaxf(acc[j][2] + bfs[cc + 0], 0.f);
            p1.y = fmaxf(acc[j][3] + bfs[cc + 1], 0.f);
            *(float2*)&y2s[r0 * 68 + cc] = p0;
            *(float2*)&y2s[r1 * 68 + cc] = p1;
        }
        __syncthreads();
        // stats + segment max/min over sorted-dst edges
        {
            int c = t & 63, g = t >> 6;
            int beg = g * 32, end = min(beg + 32, ne);
            float ps = 0.f, pq = 0.f;
            if (beg < end) {
                int cur = didx[beg];
                float val = y2s[beg * 68 + c];
                float mx = val, mn = val;
                ps += val; pq += val * val;
                for (int e = beg + 1; e < end; e++) {
                    int dd = didx[e];
                    val = y2s[e * 68 + c];
                    ps += val; pq += val * val;
                    if (dd != cur) {
                        atomicMax((unsigned int*)&nodemax[(size_t)cur * 64 + c], __float_as_uint(mx));
                        atomicMin((unsigned int*)&nodemin[(size_t)cur * 64 + c], __float_as_uint(mn));
                        cur = dd; mx = val; mn = val;
                    } else {
                        mx = fmaxf(mx, val); mn = fminf(mn, val);
                    }
                }
                atomicMax((unsigned int*)&nodemax[(size_t)cur * 64 + c], __float_as_uint(mx));
                atomicMin((unsigned int*)&nodemin[(size_t)cur * 64 + c], __float_as_uint(mn));
            }
            atomicAdd(&csum[c], ps);
            atomicAdd(&csq[c], pq);
        }
        __syncthreads();
        if (t < 64) {
            atomicAdd(&gsum[t], (double)csum[t]);
            atomicAdd(&gsq[t], (double)csq[t]);
        }
        __syncthreads();
    }
}

// ---------------- finalize: xcat = affine(max/min) with zero-fill; reset accumulators ----------------
__global__ void finalize_kernel(float* __restrict__ nodemax, float* __restrict__ nodemin,
                                const int* __restrict__ deg,
                                const float* __restrict__ s, const float* __restrict__ tt,
                                float* __restrict__ xcat, int col_off, int N) {
    int idx = blockIdx.x * 256 + threadIdx.x;
    int n = idx >> 4, q = idx & 15;
    if (n >= N) return;
    float4 mx = *(const float4*)&nodemax[(size_t)n * 64 + q * 4];
    float4 mn = *(const float4*)&nodemin[(size_t)n * 64 + q * 4];
    float4 s4 = *(const float4*)&s[q * 4];
    float4 t4 = *(const float4*)&tt[q * 4];
    float4 r = {0.f, 0.f, 0.f, 0.f};
    if (deg[n] > 0) {
        r.x = s4.x * (s4.x >= 0.f ? mx.x : mn.x) + t4.x;
        r.y = s4.y * (s4.y >= 0.f ? mx.y : mn.y) + t4.y;
        r.z = s4.z * (s4.z >= 0.f ? mx.z : mn.z) + t4.z;
        r.w = s4.w * (s4.w >= 0.f ? mx.w : mn.w) + t4.w;
    }
    *(float4*)&xcat[(size_t)n * 192 + col_off + q * 4] = r;
    // reset for next conv / next graph replay
    float big = __uint_as_float(0x7F7F7F7Fu);
    float4 z = {0.f, 0.f, 0.f, 0.f};
    float4 bg = {big, big, big, big};
    *(float4*)&nodemax[(size_t)n * 64 + q * 4] = z;
    *(float4*)&nodemin[(size_t)n * 64 + q * 4] = bg;
}

// ---------------- final: logits + log_softmax ----------------
__global__ void final_kernel(const float* __restrict__ h3, const float* __restrict__ Wf,
                             const float* __restrict__ bf, float* __restrict__ out, int N) {
    __shared__ float Ws[32 * 24];
    __shared__ float bs[24];
    __shared__ float hs[256 * 33];
    int t = threadIdx.x;
    for (int idx = t; idx < 32 * 24; idx += 256) Ws[idx] = Wf[idx];
    if (t < 24) bs[t] = bf[t];
    int n0 = blockIdx.x * 256;
    int cnt = min(256, N - n0);
    for (int idx = t; idx < cnt * 32; idx += 256) {
        int n = idx >> 5, c = idx & 31;
        hs[n * 33 + c] = h3[(size_t)(n0 + n) * 32 + c];
    }
    __syncthreads();
    float l[24];
    if (t < cnt) {
        float m = -3.4e38f;
#pragma unroll
        for (int j = 0; j < 24; j++) {
            float a = bs[j];
#pragma unroll
            for (int k = 0; k < 32; k++) a += hs[t * 33 + k] * Ws[k * 24 + j];
            l[j] = a;
            m = fmaxf(m, a);
        }
        float sum = 0.f;
#pragma unroll
        for (int j = 0; j < 24; j++) sum += __expf(l[j] - m);
        float lse = m + __logf(sum);
#pragma unroll
        for (int j = 0; j < 24; j++) l[j] -= lse;
    }
    __syncthreads();
    if (t < cnt) {
#pragma unroll
        for (int j = 0; j < 24; j++) hs[t * 33 + j] = l[j];
    }
    __syncthreads();
    for (int idx = t; idx < cnt * 24; idx += 256) {
        int n = idx / 24, j = idx % 24;
        out[(size_t)(n0 + n) * 24 + j] = hs[n * 33 + j];
    }
}

// ---------------- host orchestration ----------------
extern "C" void kernel_launch(void* const* d_in, const int* in_sizes, int n_in,
                              void* d_out, int out_size) {
    const float* x    = (const float*)d_in[0];
    const float* W1a  = (const float*)d_in[1];
    const float* b1a  = (const float*)d_in[2];
    const float* g1a  = (const float*)d_in[3];
    const float* be1a = (const float*)d_in[4];
    const float* W1b  = (const float*)d_in[5];
    const float* b1b  = (const float*)d_in[6];
    const float* g1b  = (const float*)d_in[7];
    const float* be1b = (const float*)d_in[8];
    const float* Wa   = (const float*)d_in[9];
    const float* ba   = (const float*)d_in[10];
    const float* ga   = (const float*)d_in[11];
    const float* bea  = (const float*)d_in[12];
    const float* Wb   = (const float*)d_in[13];
    const float* bb   = (const float*)d_in[14];
    const float* gb   = (const float*)d_in[15];
    const float* beb  = (const float*)d_in[16];
    const float* Wl   = (const float*)d_in[17];
    const float* bl   = (const float*)d_in[18];
    const float* gl   = (const float*)d_in[19];
    const float* bel  = (const float*)d_in[20];
    const float* Wm1  = (const float*)d_in[21];
    const float* bm1  = (const float*)d_in[22];
    const float* gm1  = (const float*)d_in[23];
    const float* bem1 = (const float*)d_in[24];
    const float* Wm2  = (const float*)d_in[25];
    const float* bm2  = (const float*)d_in[26];
    const float* gm2  = (const float*)d_in[27];
    const float* bem2 = (const float*)d_in[28];
    const float* Wo   = (const float*)d_in[29];
    const float* bo   = (const float*)d_in[30];
    const int*   eidx = (const int*)d_in[31];

    int N = in_sizes[0] / 6;
    int E = in_sizes[31] / 2;
    const int* src = eidx;
    const int* dst = eidx + E;

    float *u, *v, *nodemax, *nodemin, *xcat, *h1, *h2, *h3, *Wf, *Wft, *bf, *saff, *taff;
    double *gsum, *gsq;
    int *deg, *rowptr, *cursor, *adj_src, *adj_dst;
    cudaGetSymbolAddress((void**)&u, g_u);
    cudaGetSymbolAddress((void**)&v, g_v);
    cudaGetSymbolAddress((void**)&nodemax, g_nodemax);
    cudaGetSymbolAddress((void**)&nodemin, g_nodemin);
    cudaGetSymbolAddress((void**)&xcat, g_xcat);
    cudaGetSymbolAddress((void**)&h1, g_h1);
    cudaGetSymbolAddress((void**)&h2, g_h2);
    cudaGetSymbolAddress((void**)&h3, g_h3);
    cudaGetSymbolAddress((void**)&Wf, g_Wf);
    cudaGetSymbolAddress((void**)&Wft, g_Wft);
    cudaGetSymbolAddress((void**)&bf, g_bf);
    cudaGetSymbolAddress((void**)&saff, g_saff);
    cudaGetSymbolAddress((void**)&taff, g_taff);
    cudaGetSymbolAddress((void**)&gsum, g_sum);
    cudaGetSymbolAddress((void**)&gsq, g_sq);
    cudaGetSymbolAddress((void**)&deg, g_deg);
    cudaGetSymbolAddress((void**)&rowptr, g_rowptr);
    cudaGetSymbolAddress((void**)&cursor, g_cursor);
    cudaGetSymbolAddress((void**)&adj_src, g_adj_src);
    cudaGetSymbolAddress((void**)&adj_dst, g_adj_dst);

    cudaFuncSetAttribute(edge_gemm_agg_mma, cudaFuncAttributeMaxDynamicSharedMemorySize, EDGE_MMA_SMEM);

    // one-time init (finalize_kernel re-arms nodemax/nodemin every conv)
    cudaMemsetAsync(deg, 0, N * sizeof(int));
    cudaMemsetAsync(nodemax, 0, (size_t)N * 64 * sizeof(float));
    cudaMemsetAsync(nodemin, 0x7F, (size_t)N * 64 * sizeof(float));

    count_kernel<<<idivup(E, 256), 256>>>(dst, deg, gsum, gsq, E);
    scan_kernel<<<1, 1024>>>(deg, rowptr, cursor, N);
    scatter_kernel<<<idivup(E, 256), 256>>>(src, dst, cursor, adj_src, adj_dst, E);

    struct ConvP {
        const float* xin; int ldx; int K;
        const float *Wa_, *ba_, *ga_, *bea_, *Wb_, *bb_, *gb_, *beb_;
    };
    ConvP convs[3] = {
        { x,         6,   6,  W1a,           b1a,     g1a,     be1a,     W1b,          b1b,     g1b,     be1b     },
        { xcat,      192, 64, Wa,            ba,      ga,      bea,      Wb,           bb,      gb,      beb      },
        { xcat + 64, 192, 64, Wa + 128 * 64, ba + 64, ga + 64, bea + 64, Wb + 64 * 64, bb + 64, gb + 64, beb + 64 },
    };

    int nTiles = idivup(E, 128);
    for (int cv = 0; cv < 3; cv++) {
        const ConvP& P = convs[cv];
        gemm_uv_kernel<<<dim3(idivup(N, 64), 2), 256>>>(P.xin, P.ldx, N, P.K, P.Wa_, u, v);
        edge_stats_kernel<<<idivup(E, 256), 256>>>(u, v, adj_src, adj_dst, P.ba_, gsum, gsq, E);
        fold_kernel<<<1, 256>>>(gsum, gsq, (double)E, P.ga_, P.bea_, 64,
                                P.Wb_, P.bb_, 64, Wf, Wft, bf, (float*)0, (float*)0, 0);
        edge_gemm_agg_mma<<<296, 256, EDGE_MMA_SMEM>>>(u, v, adj_src, adj_dst, P.ba_,
                                                       Wft, bf, nodemax, nodemin,
                                                       gsum, gsq, E, nTiles);
        fold_kernel<<<1, 256>>>(gsum, gsq, (double)E, P.gb_, P.beb_, 64,
                                (const float*)0, (const float*)0, 0, (float*)0, (float*)0, (float*)0,
                                saff, taff, 1);
        finalize_kernel<<<idivup(N * 16, 256), 256>>>(nodemax, nodemin, deg, saff, taff,
                                                      xcat, cv * 64, N);
    }

    gemm_kernel<<<dim3(idivup(N, 64), 4), 256>>>(xcat, 192, N, 192, Wl, 256, 256, bl,
                                                 h1, 256, 1, 1, gsum, gsq);
    fold_kernel<<<1, 256>>>(gsum, gsq, (double)N, gl, bel, 256, Wm1, bm1, 64, Wf, (float*)0, bf,
                            (float*)0, (float*)0, 0);
    gemm_kernel<<<dim3(idivup(N, 64), 1), 256>>>(h1, 256, N, 256, Wf, 64, 64, bf,
                                                 h2, 64, 1, 1, gsum, gsq);
    fold_kernel<<<1, 256>>>(gsum, gsq, (double)N, gm1, bem1, 64, Wm2, bm2, 32, Wf, (float*)0, bf,
                            (float*)0, (float*)0, 0);
    gemm_kernel<<<dim3(idivup(N, 64), 1), 256>>>(h2, 64, N, 64, Wf, 32, 32, bf,
                                                 h3, 32, 1, 1, gsum, gsq);
    fold_kernel<<<1, 256>>>(gsum, gsq, (double)N, gm2, bem2, 32, Wo, bo, 24, Wf, (float*)0, bf,
                            (float*)0, (float*)0, 0);
    final_kernel<<<idivup(N, 256), 256>>>(h3, Wf, bf, (float*)d_out, N);
}

// round 9
// speedup vs baseline: 1.1242x; 1.0357x over previous
#include <cuda_runtime.h>
#include <cuda_bf16.h>
#include <stdint.h>
#include <math.h>

#define NN_MAX 50000
#define EE_MAX 800000

// ---------------- device scratch ----------------
__device__ float  g_u[NN_MAX * 64];
__device__ float  g_v[NN_MAX * 64];
__device__ float  g_nodemax[NN_MAX * 64];
__device__ float  g_nodemin[NN_MAX * 64];
__device__ float  g_xcat[NN_MAX * 192];
__device__ float  g_h1[NN_MAX * 256];
__device__ float  g_h2[NN_MAX * 64];
__device__ float  g_h3[NN_MAX * 32];
__device__ double g_sum[256];
__device__ double g_sq[256];
__device__ float  g_Wf[256 * 64];
__device__ float  g_Wft[64 * 64];
__device__ float  g_bf[256];
__device__ float  g_saff[64], g_taff[64];
__device__ int    g_deg[NN_MAX], g_rowptr[NN_MAX + 1], g_cursor[NN_MAX];
__device__ int    g_adj_src[EE_MAX], g_adj_dst[EE_MAX];

static inline int idivup(int a, int b) { return (a + b - 1) / b; }

// packed fp32x2 FMA
__device__ __forceinline__ void ffma2(unsigned long long& acc, unsigned long long a, unsigned long long b) {
    asm("fma.rn.f32x2 %0, %1, %2, %0;" : "+l"(acc) : "l"(a), "l"(b));
}
union U64F2 { unsigned long long u; float2 f; };

#define SW128(off) ((off) ^ (((off) >> 3) & 0x70))

// warp-level bf16 MMA, m16n8k16, fp32 accumulate
__device__ __forceinline__ void mma_bf16(float* d, const uint32_t* a, uint32_t b0, uint32_t b1) {
    asm volatile(
        "mma.sync.aligned.m16n8k16.row.col.f32.bf16.bf16.f32 "
        "{%0,%1,%2,%3}, {%4,%5,%6,%7}, {%8,%9}, {%0,%1,%2,%3};"
        : "+f"(d[0]), "+f"(d[1]), "+f"(d[2]), "+f"(d[3])
        : "r"(a[0]), "r"(a[1]), "r"(a[2]), "r"(a[3]), "r"(b0), "r"(b1));
}

// ---------------- CSR build ----------------
__global__ void count_kernel(const int* __restrict__ dst, int* __restrict__ deg,
                             double* __restrict__ gsum, double* __restrict__ gsq, int E) {
    if (blockIdx.x == 0 && threadIdx.x < 256) { gsum[threadIdx.x] = 0.0; gsq[threadIdx.x] = 0.0; }
    int e = blockIdx.x * 256 + threadIdx.x;
    if (e < E) atomicAdd(&deg[dst[e]], 1);
}

__global__ void scan_kernel(const int* __restrict__ deg, int* __restrict__ rowptr,
                            int* __restrict__ cursor, int N) {
    __shared__ int warpsum[32];
    __shared__ int soff;
    int t = threadIdx.x, lane = t & 31, wid = t >> 5;
    if (t == 0) { soff = 0; rowptr[0] = 0; }
    __syncthreads();
    for (int base = 0; base < N; base += 1024) {
        int x = (base + t < N) ? deg[base + t] : 0;
        int v = x;
#pragma unroll
        for (int d = 1; d < 32; d <<= 1) {
            int y = __shfl_up_sync(0xffffffffu, v, d);
            if (lane >= d) v += y;
        }
        if (lane == 31) warpsum[wid] = v;
        __syncthreads();
        if (wid == 0) {
            int s = warpsum[lane];
#pragma unroll
            for (int d = 1; d < 32; d <<= 1) {
                int y = __shfl_up_sync(0xffffffffu, s, d);
                if (lane >= d) s += y;
            }
            warpsum[lane] = s;
        }
        __syncthreads();
        int inc = v + (wid > 0 ? warpsum[wid - 1] : 0) + soff;
        if (base + t < N) { rowptr[base + t + 1] = inc; cursor[base + t] = inc - x; }
        __syncthreads();
        if (t == 1023) soff = inc;
        __syncthreads();
    }
}

// scatter sorted src/dst VALUES -> later passes read them linearly
__global__ void scatter_kernel(const int* __restrict__ src, const int* __restrict__ dst,
                               int* __restrict__ cursor,
                               int* __restrict__ adj_src, int* __restrict__ adj_dst, int E) {
    int e = blockIdx.x * 256 + threadIdx.x;
    if (e < E) {
        int d = dst[e];
        int pos = atomicAdd(&cursor[d], 1);
        adj_src[pos] = src[e];
        adj_dst[pos] = d;
    }
}

// ---------------- node GEMM: u = X @ (Wtop - Wbot), v = X @ Wbot ----------------
__global__ void gemm_uv_kernel(const float* __restrict__ X, int ldx, int R, int K,
                               const float* __restrict__ Wa,
                               float* __restrict__ u, float* __restrict__ v) {
    __shared__ float Xs[64 * 32];
    __shared__ float Ws[64 * 32];
    int t = threadIdx.x;
    int tx = t & 15, ty = t >> 4;
    int r0 = blockIdx.x * 64;
    int mode = blockIdx.y;
    float* Y = mode ? v : u;
    unsigned long long acc[4][4];
#pragma unroll
    for (int i = 0; i < 4; i++)
#pragma unroll
        for (int j = 0; j < 4; j++) acc[i][j] = 0ULL;

    for (int kc = 0; kc < K; kc += 32) {
        for (int idx = t; idx < 64 * 32; idx += 256) {
            int r = idx >> 5, k = idx & 31;
            int gr = r0 + r, gk = kc + k;
            Xs[idx] = (gr < R && gk < K) ? X[(size_t)gr * ldx + gk] : 0.f;
        }
        for (int idx = t; idx < 64 * 32; idx += 256) {
            int k = idx >> 6, c = idx & 63;
            int gk = kc + k;
            float vv = 0.f;
            if (gk < K) {
                float wb = Wa[(size_t)(K + gk) * 64 + c];
                vv = mode ? wb : (Wa[(size_t)gk * 64 + c] - wb);
            }
            int chunk = ((k >> 2) + (c >> 2)) & 7;
            Ws[c * 32 + chunk * 4 + (k & 3)] = vv;
        }
        __syncthreads();
#pragma unroll
        for (int kk = 0; kk < 32; kk += 4) {
            int k4 = kk >> 2;
            ulonglong2 w[4], e[4];
#pragma unroll
            for (int j = 0; j < 4; j++) {
                int chunk = (k4 + tx) & 7;
                w[j] = *(const ulonglong2*)&Ws[(tx * 4 + j) * 32 + chunk * 4];
            }
#pragma unroll
            for (int i = 0; i < 4; i++)
                e[i] = *(const ulonglong2*)&Xs[(ty * 4 + i) * 32 + kk];
#pragma unroll
            for (int i = 0; i < 4; i++)
#pragma unroll
                for (int j = 0; j < 4; j++) {
                    ffma2(acc[i][j], e[i].x, w[j].x);
                    ffma2(acc[i][j], e[i].y, w[j].y);
                }
        }
        __syncthreads();
    }
#pragma unroll
    for (int i = 0; i < 4; i++) {
        int gr = r0 + ty * 4 + i;
        if (gr >= R) continue;
        float4 r4;
        U64F2 u0, u1, u2, u3;
        u0.u = acc[i][0]; u1.u = acc[i][1]; u2.u = acc[i][2]; u3.u = acc[i][3];
        r4.x = u0.f.x + u0.f.y; r4.y = u1.f.x + u1.f.y;
        r4.z = u2.f.x + u2.f.y; r4.w = u3.f.x + u3.f.y;
        *(float4*)&Y[(size_t)gr * 64 + tx * 4] = r4;
    }
}

// ---------------- generic GEMM for head ----------------
__global__ void gemm_kernel(const float* __restrict__ X, int ldx, int R, int K,
                            const float* __restrict__ W, int ldw, int CO,
                            const float* __restrict__ bias,
                            float* __restrict__ Y, int ldy,
                            int do_relu, int do_stats,
                            double* __restrict__ gsum, double* __restrict__ gsq) {
    __shared__ float Xs[64 * 32];
    __shared__ float Ws[64 * 32];
    __shared__ float csum[64], csq[64];
    int t = threadIdx.x;
    int tx = t & 15, ty = t >> 4;
    int r0 = blockIdx.x * 64;
    int c0 = blockIdx.y * 64;
    if (do_stats && t < 64) { csum[t] = 0.f; csq[t] = 0.f; }
    unsigned long long acc[4][4];
#pragma unroll
    for (int i = 0; i < 4; i++)
#pragma unroll
        for (int j = 0; j < 4; j++) acc[i][j] = 0ULL;

    for (int kc = 0; kc < K; kc += 32) {
        for (int idx = t; idx < 64 * 32; idx += 256) {
            int r = idx >> 5, k = idx & 31;
            int gr = r0 + r, gk = kc + k;
            Xs[idx] = (gr < R && gk < K) ? X[(size_t)gr * ldx + gk] : 0.f;
        }
        for (int idx = t; idx < 64 * 32; idx += 256) {
            int k = idx >> 6, c = idx & 63;
            int gk = kc + k, gc = c0 + c;
            float vv = (gk < K && gc < CO) ? W[(size_t)gk * ldw + gc] : 0.f;
            int chunk = ((k >> 2) + (c >> 2)) & 7;
            Ws[c * 32 + chunk * 4 + (k & 3)] = vv;
        }
        __syncthreads();
#pragma unroll
        for (int kk = 0; kk < 32; kk += 4) {
            int k4 = kk >> 2;
            ulonglong2 w[4], e[4];
#pragma unroll
            for (int j = 0; j < 4; j++) {
                int chunk = (k4 + tx) & 7;
                w[j] = *(const ulonglong2*)&Ws[(tx * 4 + j) * 32 + chunk * 4];
            }
#pragma unroll
            for (int i = 0; i < 4; i++)
                e[i] = *(const ulonglong2*)&Xs[(ty * 4 + i) * 32 + kk];
#pragma unroll
            for (int i = 0; i < 4; i++)
#pragma unroll
                for (int j = 0; j < 4; j++) {
                    ffma2(acc[i][j], e[i].x, w[j].x);
                    ffma2(acc[i][j], e[i].y, w[j].y);
                }
        }
        __syncthreads();
    }

    float ps[4] = {0.f, 0.f, 0.f, 0.f}, pq[4] = {0.f, 0.f, 0.f, 0.f};
#pragma unroll
    for (int i = 0; i < 4; i++) {
        int gr = r0 + ty * 4 + i;
        if (gr >= R) continue;
#pragma unroll
        for (int j = 0; j < 4; j++) {
            int gc = c0 + tx * 4 + j;
            if (gc >= CO) continue;
            U64F2 uu; uu.u = acc[i][j];
            float vv = uu.f.x + uu.f.y;
            if (bias) vv += bias[gc];
            if (do_relu) vv = fmaxf(vv, 0.f);
            Y[(size_t)gr * ldy + gc] = vv;
            ps[j] += vv; pq[j] += vv * vv;
        }
    }
    if (do_stats) {
        __syncthreads();
#pragma unroll
        for (int j = 0; j < 4; j++) {
            atomicAdd(&csum[tx * 4 + j], ps[j]);
            atomicAdd(&csq[tx * 4 + j], pq[j]);
        }
        __syncthreads();
        if (t < 64 && c0 + t < CO) {
            atomicAdd(&gsum[c0 + t], (double)csum[t]);
            atomicAdd(&gsq[c0 + t], (double)csq[t]);
        }
    }
}

// ---------------- edge stats pass (sorted, linear index reads, MLP-batched) ----------------
__global__ void edge_stats_kernel(const float* __restrict__ u, const float* __restrict__ v,
                                  const int* __restrict__ adj_src, const int* __restrict__ adj_dst,
                                  const float* __restrict__ ba,
                                  double* __restrict__ gsum, double* __restrict__ gsq, int E) {
    __shared__ float csum[64], csq[64];
    __shared__ int sidx[256], didx[256];
    int t = threadIdx.x;
    int e0 = blockIdx.x * 256;
    int ne = min(256, E - e0);
    if (t < ne) { sidx[t] = adj_src[e0 + t]; didx[t] = adj_dst[e0 + t]; }
    if (t < 64) { csum[t] = 0.f; csq[t] = 0.f; }
    __syncthreads();
    int q = t & 15, eg = t >> 4;
    float4 b4 = *(const float4*)&ba[q * 4];
    float4 ps = {0.f, 0.f, 0.f, 0.f}, pq = {0.f, 0.f, 0.f, 0.f};
    if (ne == 256) {
        // full tile: batch loads (4 edges per thread in flight) before accumulating
#pragma unroll
        for (int base = 0; base < 16; base += 4) {
            float4 uu[4], vv[4];
#pragma unroll
            for (int it = 0; it < 4; it++) {
                int e = eg + (base + it) * 16;
                uu[it] = *(const float4*)&u[(size_t)didx[e] * 64 + q * 4];
                vv[it] = *(const float4*)&v[(size_t)sidx[e] * 64 + q * 4];
            }
#pragma unroll
            for (int it = 0; it < 4; it++) {
                float a0 = fmaxf(uu[it].x + vv[it].x + b4.x, 0.f);
                float a1 = fmaxf(uu[it].y + vv[it].y + b4.y, 0.f);
                float a2 = fmaxf(uu[it].z + vv[it].z + b4.z, 0.f);
                float a3 = fmaxf(uu[it].w + vv[it].w + b4.w, 0.f);
                ps.x += a0; pq.x += a0 * a0;
                ps.y += a1; pq.y += a1 * a1;
                ps.z += a2; pq.z += a2 * a2;
                ps.w += a3; pq.w += a3 * a3;
            }
        }
    } else {
        for (int e = eg; e < ne; e += 16) {
            float4 u4 = *(const float4*)&u[(size_t)didx[e] * 64 + q * 4];
            float4 v4 = *(const float4*)&v[(size_t)sidx[e] * 64 + q * 4];
            float a0 = fmaxf(u4.x + v4.x + b4.x, 0.f);
            float a1 = fmaxf(u4.y + v4.y + b4.y, 0.f);
            float a2 = fmaxf(u4.z + v4.z + b4.z, 0.f);
            float a3 = fmaxf(u4.w + v4.w + b4.w, 0.f);
            ps.x += a0; pq.x += a0 * a0;
            ps.y += a1; pq.y += a1 * a1;
            ps.z += a2; pq.z += a2 * a2;
            ps.w += a3; pq.w += a3 * a3;
        }
    }
    atomicAdd(&csum[q * 4 + 0], ps.x); atomicAdd(&csq[q * 4 + 0], pq.x);
    atomicAdd(&csum[q * 4 + 1], ps.y); atomicAdd(&csq[q * 4 + 1], pq.y);
    atomicAdd(&csum[q * 4 + 2], ps.z); atomicAdd(&csq[q * 4 + 2], pq.z);
    atomicAdd(&csum[q * 4 + 3], ps.w); atomicAdd(&csq[q * 4 + 3], pq.w);
    __syncthreads();
    if (t < 64) {
        atomicAdd(&gsum[t], (double)csum[t]);
        atomicAdd(&gsq[t], (double)csq[t]);
    }
}

// ---------------- BN fold ----------------
__global__ void fold_kernel(double* __restrict__ gsum, double* __restrict__ gsq, double count,
                            const float* __restrict__ gamma, const float* __restrict__ beta, int CH,
                            const float* __restrict__ Wn, const float* __restrict__ bn_, int COn,
                            float* __restrict__ Wf, float* __restrict__ Wft, float* __restrict__ bf,
                            float* __restrict__ saff, float* __restrict__ taff, int mode) {
    __shared__ float ss[256], tt[256];
    int t = threadIdx.x;
    if (t < CH) {
        double mu = gsum[t] / count;
        double var = gsq[t] / count - mu * mu;
        if (var < 0.0) var = 0.0;
        float sc = gamma[t] * rsqrtf((float)var + 1e-5f);
        ss[t] = sc;
        tt[t] = beta[t] - (float)mu * sc;
        gsum[t] = 0.0; gsq[t] = 0.0;
    }
    __syncthreads();
    if (mode == 1) {
        if (t < CH) { saff[t] = ss[t]; taff[t] = tt[t]; }
        return;
    }
    for (int idx = t; idx < CH * COn; idx += 256)
        Wf[idx] = ss[idx / COn] * Wn[idx];
    if (Wft) {
        for (int idx = t; idx < CH * COn; idx += 256) {
            int c = idx >> 6, k = idx & 63;
            Wft[idx] = ss[k] * Wn[k * COn + c];
        }
    }
    if (t < COn) {
        float a = bn_[t];
        for (int c = 0; c < CH; c++) a += tt[c] * Wn[c * COn + t];
        bf[t] = a;
    }
}

// ---------------- HMMA fused edge GEMM + segment max/min (persistent) ----------------
// dyn smem (1024-aligned): A_hi 16K | A_lo 16K | B_hi 8K | B_lo 8K | y2s 128*68*4
#define EDGE_MMA_SMEM (83968 + 1024)
__global__ void __launch_bounds__(256, 2)
edge_gemm_agg_mma(const float* __restrict__ u, const float* __restrict__ v,
                  const int* __restrict__ adj_src, const int* __restrict__ adj_dst,
                  const float* __restrict__ ba,
                  const float* __restrict__ Wft, const float* __restrict__ bf,
                  float* __restrict__ nodemax, float* __restrict__ nodemin,
                  double* __restrict__ gsum, double* __restrict__ gsq,
                  int E, int nTiles) {
    extern __shared__ char dynraw[];
    __shared__ int sidx[128], didx[128];
    __shared__ float bas[64], bfs[64], csum[64], csq[64];

    uintptr_t rawp = (uintptr_t)dynraw;
    char* dynp = dynraw + ((1024u - (rawp & 1023u)) & 1023u);

    char* A_hi = dynp;
    char* A_lo = dynp + 16384;
    char* B_hi = dynp + 32768;
    char* B_lo = dynp + 40960;
    float* y2s = (float*)(dynp + 49152);   // [128][68]

    int t = threadIdx.x;
    int wid = t >> 5, lane = t & 31;
    int grp = lane >> 2, tig = lane & 3;

    if (t < 64) { bas[t] = ba[t]; bfs[t] = bf[t]; }
    // build B_hi/B_lo from Wft [n][k] fp32, SW128-swizzled 128B rows
    for (int idx = t; idx < 64 * 64; idx += 256) {
        int n = idx >> 6, k = idx & 63;
        float w = Wft[idx];
        __nv_bfloat16 h = __float2bfloat16(w);
        __nv_bfloat16 l = __float2bfloat16(w - __bfloat162float(h));
        uint32_t off = SW128((uint32_t)(n * 128 + k * 2));
        *(unsigned short*)(B_hi + off) = __bfloat16_as_ushort(h);
        *(unsigned short*)(B_lo + off) = __bfloat16_as_ushort(l);
    }
    __syncthreads();

    for (int tile = blockIdx.x; tile < nTiles; tile += gridDim.x) {
        int e0 = tile * 128;
        int ne = min(128, E - e0);
        if (t < ne) {
            sidx[t] = adj_src[e0 + t];
            didx[t] = adj_dst[e0 + t];
        }
        if (t < 64) { csum[t] = 0.f; csq[t] = 0.f; }
        __syncthreads();
        // gather y1, split to bf16 hi/lo, SW128 layout — batched loads (MLP 8)
#pragma unroll
        for (int half = 0; half < 2; half++) {
            float4 uu[4], vv[4];
#pragma unroll
            for (int it = 0; it < 4; it++) {
                int idx = t + (half * 4 + it) * 256;
                int e = idx >> 4, q = idx & 15;
                if (e < ne) {
                    uu[it] = *(const float4*)&u[(size_t)didx[e] * 64 + q * 4];
                    vv[it] = *(const float4*)&v[(size_t)sidx[e] * 64 + q * 4];
                } else {
                    uu[it] = make_float4(0.f, 0.f, 0.f, 0.f);
                    vv[it] = make_float4(0.f, 0.f, 0.f, 0.f);
                }
            }
#pragma unroll
            for (int it = 0; it < 4; it++) {
                int idx = t + (half * 4 + it) * 256;
                int e = idx >> 4, q = idx & 15;
                float4 y = {0.f, 0.f, 0.f, 0.f};
                if (e < ne) {
                    float4 b4 = *(const float4*)&bas[q * 4];
                    y.x = fmaxf(uu[it].x + vv[it].x + b4.x, 0.f);
                    y.y = fmaxf(uu[it].y + vv[it].y + b4.y, 0.f);
                    y.z = fmaxf(uu[it].z + vv[it].z + b4.z, 0.f);
                    y.w = fmaxf(uu[it].w + vv[it].w + b4.w, 0.f);
                }
                __nv_bfloat16 h0 = __float2bfloat16(y.x), h1 = __float2bfloat16(y.y);
                __nv_bfloat16 h2 = __float2bfloat16(y.z), h3 = __float2bfloat16(y.w);
                float l0f = y.x - __bfloat162float(h0), l1f = y.y - __bfloat162float(h1);
                float l2f = y.z - __bfloat162float(h2), l3f = y.w - __bfloat162float(h3);
                uint2 hp, lp;
                hp.x = (uint32_t)__bfloat16_as_ushort(h0) | ((uint32_t)__bfloat16_as_ushort(h1) << 16);
                hp.y = (uint32_t)__bfloat16_as_ushort(h2) | ((uint32_t)__bfloat16_as_ushort(h3) << 16);
                lp.x = (uint32_t)__bfloat16_as_ushort(__float2bfloat16(l0f)) |
                       ((uint32_t)__bfloat16_as_ushort(__float2bfloat16(l1f)) << 16);
                lp.y = (uint32_t)__bfloat16_as_ushort(__float2bfloat16(l2f)) |
                       ((uint32_t)__bfloat16_as_ushort(__float2bfloat16(l3f)) << 16);
                uint32_t off = SW128((uint32_t)(e * 128 + q * 8));
                *(uint2*)(A_hi + off) = hp;
                *(uint2*)(A_lo + off) = lp;
            }
        }
        __syncthreads();

        // warp-level MMA: warp w -> rows 16w..16w+15, all 64 cols
        float acc[8][4];
#pragma unroll
        for (int j = 0; j < 8; j++)
#pragma unroll
            for (int q = 0; q < 4; q++) acc[j][q] = 0.f;

        int r0 = wid * 16 + grp;
        int r1 = r0 + 8;
#pragma unroll
        for (int ks = 0; ks < 4; ks++) {
            int c0 = ks * 32 + tig * 4;
            int c1 = c0 + 16;
            uint32_t ahi[4], alo[4];
            ahi[0] = *(const uint32_t*)(A_hi + SW128((uint32_t)(r0 * 128 + c0)));
            ahi[1] = *(const uint32_t*)(A_hi + SW128((uint32_t)(r1 * 128 + c0)));
            ahi[2] = *(const uint32_t*)(A_hi + SW128((uint32_t)(r0 * 128 + c1)));
            ahi[3] = *(const uint32_t*)(A_hi + SW128((uint32_t)(r1 * 128 + c1)));
            alo[0] = *(const uint32_t*)(A_lo + SW128((uint32_t)(r0 * 128 + c0)));
            alo[1] = *(const uint32_t*)(A_lo + SW128((uint32_t)(r1 * 128 + c0)));
            alo[2] = *(const uint32_t*)(A_lo + SW128((uint32_t)(r0 * 128 + c1)));
            alo[3] = *(const uint32_t*)(A_lo + SW128((uint32_t)(r1 * 128 + c1)));
#pragma unroll
            for (int j = 0; j < 8; j++) {
                int n0 = j * 8 + grp;
                uint32_t o0 = SW128((uint32_t)(n0 * 128 + c0));
                uint32_t o1 = SW128((uint32_t)(n0 * 128 + c1));
                uint32_t bhi0 = *(const uint32_t*)(B_hi + o0);
                uint32_t bhi1 = *(const uint32_t*)(B_hi + o1);
                uint32_t blo0 = *(const uint32_t*)(B_lo + o0);
                uint32_t blo1 = *(const uint32_t*)(B_lo + o1);
                mma_bf16(acc[j], ahi, bhi0, bhi1);
                mma_bf16(acc[j], ahi, blo0, blo1);
                mma_bf16(acc[j], alo, bhi0, bhi1);
            }
        }
        // epilogue: bias + relu, write to y2s (stride 68 -> conflict-free)
#pragma unroll
        for (int j = 0; j < 8; j++) {
            int cc = j * 8 + tig * 2;
            float2 p0, p1;
            p0.x = fmaxf(acc[j][0] + bfs[cc + 0], 0.f);
            p0.y = fmaxf(acc[j][1] + bfs[cc + 1], 0.f);
            p1.x = fmaxf(acc[j][2] + bfs[cc + 0], 0.f);
            p1.y = fmaxf(acc[j][3] + bfs[cc + 1], 0.f);
            *(float2*)&y2s[r0 * 68 + cc] = p0;
            *(float2*)&y2s[r1 * 68 + cc] = p1;
        }
        __syncthreads();
        // stats + segment max/min; interior (complete) segments -> plain store, boundary -> atomic
        {
            int c = t & 63, g = t >> 6;
            int beg = g * 32, end = min(beg + 32, ne);
            float ps = 0.f, pq = 0.f;
            if (beg < end) {
                int cur = didx[beg];
                // does the first segment continue from before this group?
                bool openHead;
                if (beg == 0) openHead = (e0 > 0);              // unknown previous tile -> assume open
                else          openHead = (didx[beg - 1] == cur); // previous edge in same tile
                float val = y2s[beg * 68 + c];
                float mx = val, mn = val;
                ps += val; pq += val * val;
                for (int e = beg + 1; e < end; e++) {
                    int dd = didx[e];
                    val = y2s[e * 68 + c];
                    ps += val; pq += val * val;
                    if (dd != cur) {
                        // segment closed inside group: tail is closed
                        if (!openHead) {
                            nodemax[(size_t)cur * 64 + c] = mx;
                            nodemin[(size_t)cur * 64 + c] = mn;
                        } else {
                            atomicMax((unsigned int*)&nodemax[(size_t)cur * 64 + c], __float_as_uint(mx));
                            atomicMin((unsigned int*)&nodemin[(size_t)cur * 64 + c], __float_as_uint(mn));
                        }
                        openHead = false;
                        cur = dd; mx = val; mn = val;
                    } else {
                        mx = fmaxf(mx, val); mn = fminf(mn, val);
                    }
                }
                // final segment: tail open if it extends past this group
                bool tailOpen;
                if (end == ne) tailOpen = (e0 + ne < E);         // next tile unknown
                else           tailOpen = (didx[end] == cur);    // next edge in same tile
                if (!openHead && !tailOpen) {
                    nodemax[(size_t)cur * 64 + c] = mx;
                    nodemin[(size_t)cur * 64 + c] = mn;
                } else {
                    atomicMax((unsigned int*)&nodemax[(size_t)cur * 64 + c], __float_as_uint(mx));
                    atomicMin((unsigned int*)&nodemin[(size_t)cur * 64 + c], __float_as_uint(mn));
                }
            }
            atomicAdd(&csum[c], ps);
            atomicAdd(&csq[c], pq);
        }
        __syncthreads();
        if (t < 64) {
            atomicAdd(&gsum[t], (double)csum[t]);
            atomicAdd(&gsq[t], (double)csq[t]);
        }
        __syncthreads();
    }
}

// ---------------- finalize: xcat = affine(max/min) with zero-fill; reset accumulators ----------------
__global__ void finalize_kernel(float* __restrict__ nodemax, float* __restrict__ nodemin,
                                const int* __restrict__ deg,
                                const float* __restrict__ s, const float* __restrict__ tt,
                                float* __restrict__ xcat, int col_off, int N) {
    int idx = blockIdx.x * 256 + threadIdx.x;
    int n = idx >> 4, q = idx & 15;
    if (n >= N) return;
    float4 mx = *(const float4*)&nodemax[(size_t)n * 64 + q * 4];
    float4 mn = *(const float4*)&nodemin[(size_t)n * 64 + q * 4];
    float4 s4 = *(const float4*)&s[q * 4];
    float4 t4 = *(const float4*)&tt[q * 4];
    float4 r = {0.f, 0.f, 0.f, 0.f};
    if (deg[n] > 0) {
        r.x = s4.x * (s4.x >= 0.f ? mx.x : mn.x) + t4.x;
        r.y = s4.y * (s4.y >= 0.f ? mx.y : mn.y) + t4.y;
        r.z = s4.z * (s4.z >= 0.f ? mx.z : mn.z) + t4.z;
        r.w = s4.w * (s4.w >= 0.f ? mx.w : mn.w) + t4.w;
    }
    *(float4*)&xcat[(size_t)n * 192 + col_off + q * 4] = r;
    // reset for next conv / next graph replay
    float big = __uint_as_float(0x7F7F7F7Fu);
    float4 z = {0.f, 0.f, 0.f, 0.f};
    float4 bg = {big, big, big, big};
    *(float4*)&nodemax[(size_t)n * 64 + q * 4] = z;
    *(float4*)&nodemin[(size_t)n * 64 + q * 4] = bg;
}

// ---------------- final: logits + log_softmax ----------------
__global__ void final_kernel(const float* __restrict__ h3, const float* __restrict__ Wf,
                             const float* __restrict__ bf, float* __restrict__ out, int N) {
    __shared__ float Ws[32 * 24];
    __shared__ float bs[24];
    __shared__ float hs[256 * 33];
    int t = threadIdx.x;
    for (int idx = t; idx < 32 * 24; idx += 256) Ws[idx] = Wf[idx];
    if (t < 24) bs[t] = bf[t];
    int n0 = blockIdx.x * 256;
    int cnt = min(256, N - n0);
    for (int idx = t; idx < cnt * 32; idx += 256) {
        int n = idx >> 5, c = idx & 31;
        hs[n * 33 + c] = h3[(size_t)(n0 + n) * 32 + c];
    }
    __syncthreads();
    float l[24];
    if (t < cnt) {
        float m = -3.4e38f;
#pragma unroll
        for (int j = 0; j < 24; j++) {
            float a = bs[j];
#pragma unroll
            for (int k = 0; k < 32; k++) a += hs[t * 33 + k] * Ws[k * 24 + j];
            l[j] = a;
            m = fmaxf(m, a);
        }
        float sum = 0.f;
#pragma unroll
        for (int j = 0; j < 24; j++) sum += __expf(l[j] - m);
        float lse = m + __logf(sum);
#pragma unroll
        for (int j = 0; j < 24; j++) l[j] -= lse;
    }
    __syncthreads();
    if (t < cnt) {
#pragma unroll
        for (int j = 0; j < 24; j++) hs[t * 33 + j] = l[j];
    }
    __syncthreads();
    for (int idx = t; idx < cnt * 24; idx += 256) {
        int n = idx / 24, j = idx % 24;
        out[(size_t)(n0 + n) * 24 + j] = hs[n * 33 + j];
    }
}

// ---------------- host orchestration ----------------
extern "C" void kernel_launch(void* const* d_in, const int* in_sizes, int n_in,
                              void* d_out, int out_size) {
    const float* x    = (const float*)d_in[0];
    const float* W1a  = (const float*)d_in[1];
    const float* b1a  = (const float*)d_in[2];
    const float* g1a  = (const float*)d_in[3];
    const float* be1a = (const float*)d_in[4];
    const float* W1b  = (const float*)d_in[5];
    const float* b1b  = (const float*)d_in[6];
    const float* g1b  = (const float*)d_in[7];
    const float* be1b = (const float*)d_in[8];
    const float* Wa   = (const float*)d_in[9];
    const float* ba   = (const float*)d_in[10];
    const float* ga   = (const float*)d_in[11];
    const float* bea  = (const float*)d_in[12];
    const float* Wb   = (const float*)d_in[13];
    const float* bb   = (const float*)d_in[14];
    const float* gb   = (const float*)d_in[15];
    const float* beb  = (const float*)d_in[16];
    const float* Wl   = (const float*)d_in[17];
    const float* bl   = (const float*)d_in[18];
    const float* gl   = (const float*)d_in[19];
    const float* bel  = (const float*)d_in[20];
    const float* Wm1  = (const float*)d_in[21];
    const float* bm1  = (const float*)d_in[22];
    const float* gm1  = (const float*)d_in[23];
    const float* bem1 = (const float*)d_in[24];
    const float* Wm2  = (const float*)d_in[25];
    const float* bm2  = (const float*)d_in[26];
    const float* gm2  = (const float*)d_in[27];
    const float* bem2 = (const float*)d_in[28];
    const float* Wo   = (const float*)d_in[29];
    const float* bo   = (const float*)d_in[30];
    const int*   eidx = (const int*)d_in[31];

    int N = in_sizes[0] / 6;
    int E = in_sizes[31] / 2;
    const int* src = eidx;
    const int* dst = eidx + E;

    float *u, *v, *nodemax, *nodemin, *xcat, *h1, *h2, *h3, *Wf, *Wft, *bf, *saff, *taff;
    double *gsum, *gsq;
    int *deg, *rowptr, *cursor, *adj_src, *adj_dst;
    cudaGetSymbolAddress((void**)&u, g_u);
    cudaGetSymbolAddress((void**)&v, g_v);
    cudaGetSymbolAddress((void**)&nodemax, g_nodemax);
    cudaGetSymbolAddress((void**)&nodemin, g_nodemin);
    cudaGetSymbolAddress((void**)&xcat, g_xcat);
    cudaGetSymbolAddress((void**)&h1, g_h1);
    cudaGetSymbolAddress((void**)&h2, g_h2);
    cudaGetSymbolAddress((void**)&h3, g_h3);
    cudaGetSymbolAddress((void**)&Wf, g_Wf);
    cudaGetSymbolAddress((void**)&Wft, g_Wft);
    cudaGetSymbolAddress((void**)&bf, g_bf);
    cudaGetSymbolAddress((void**)&saff, g_saff);
    cudaGetSymbolAddress((void**)&taff, g_taff);
    cudaGetSymbolAddress((void**)&gsum, g_sum);
    cudaGetSymbolAddress((void**)&gsq, g_sq);
    cudaGetSymbolAddress((void**)&deg, g_deg);
    cudaGetSymbolAddress((void**)&rowptr, g_rowptr);
    cudaGetSymbolAddress((void**)&cursor, g_cursor);
    cudaGetSymbolAddress((void**)&adj_src, g_adj_src);
    cudaGetSymbolAddress((void**)&adj_dst, g_adj_dst);

    cudaFuncSetAttribute(edge_gemm_agg_mma, cudaFuncAttributeMaxDynamicSharedMemorySize, EDGE_MMA_SMEM);

    cudaMemsetAsync(deg, 0, N * sizeof(int));
    cudaMemsetAsync(nodemax, 0, (size_t)N * 64 * sizeof(float));
    cudaMemsetAsync(nodemin, 0x7F, (size_t)N * 64 * sizeof(float));

    count_kernel<<<idivup(E, 256), 256>>>(dst, deg, gsum, gsq, E);
    scan_kernel<<<1, 1024>>>(deg, rowptr, cursor, N);
    scatter_kernel<<<idivup(E, 256), 256>>>(src, dst, cursor, adj_src, adj_dst, E);

    struct ConvP {
        const float* xin; int ldx; int K;
        const float *Wa_, *ba_, *ga_, *bea_, *Wb_, *bb_, *gb_, *beb_;
    };
    ConvP convs[3] = {
        { x,         6,   6,  W1a,           b1a,     g1a,     be1a,     W1b,          b1b,     g1b,     be1b     },
        { xcat,      192, 64, Wa,            ba,      ga,      bea,      Wb,           bb,      gb,      beb      },
        { xcat + 64, 192, 64, Wa + 128 * 64, ba + 64, ga + 64, bea + 64, Wb + 64 * 64, bb + 64, gb + 64, beb + 64 },
    };

    int nTiles = idivup(E, 128);
    for (int cv = 0; cv < 3; cv++) {
        const ConvP& P = convs[cv];
        gemm_uv_kernel<<<dim3(idivup(N, 64), 2), 256>>>(P.xin, P.ldx, N, P.K, P.Wa_, u, v);
        edge_stats_kernel<<<idivup(E, 256), 256>>>(u, v, adj_src, adj_dst, P.ba_, gsum, gsq, E);
        fold_kernel<<<1, 256>>>(gsum, gsq, (double)E, P.ga_, P.bea_, 64,
                                P.Wb_, P.bb_, 64, Wf, Wft, bf, (float*)0, (float*)0, 0);
        edge_gemm_agg_mma<<<296, 256, EDGE_MMA_SMEM>>>(u, v, adj_src, adj_dst, P.ba_,
                                                       Wft, bf, nodemax, nodemin,
                                                       gsum, gsq, E, nTiles);
        fold_kernel<<<1, 256>>>(gsum, gsq, (double)E, P.gb_, P.beb_, 64,
                                (const float*)0, (const float*)0, 0, (float*)0, (float*)0, (float*)0,
                                saff, taff, 1);
        finalize_kernel<<<idivup(N * 16, 256), 256>>>(nodemax, nodemin, deg, saff, taff,
                                                      xcat, cv * 64, N);
    }

    gemm_kernel<<<dim3(idivup(N, 64), 4), 256>>>(xcat, 192, N, 192, Wl, 256, 256, bl,
                                                 h1, 256, 1, 1, gsum, gsq);
    fold_kernel<<<1, 256>>>(gsum, gsq, (double)N, gl, bel, 256, Wm1, bm1, 64, Wf, (float*)0, bf,
                            (float*)0, (float*)0, 0);
    gemm_kernel<<<dim3(idivup(N, 64), 1), 256>>>(h1, 256, N, 256, Wf, 64, 64, bf,
                                                 h2, 64, 1, 1, gsum, gsq);
    fold_kernel<<<1, 256>>>(gsum, gsq, (double)N, gm1, bem1, 64, Wm2, bm2, 32, Wf, (float*)0, bf,
                            (float*)0, (float*)0, 0);
    gemm_kernel<<<dim3(idivup(N, 64), 1), 256>>>(h2, 64, N, 64, Wf, 32, 32, bf,
                                                 h3, 32, 1, 1, gsum, gsq);
    fold_kernel<<<1, 256>>>(gsum, gsq, (double)N, gm2, bem2, 32, Wo, bo, 24, Wf, (float*)0, bf,
                            (float*)0, (float*)0, 0);
    final_kernel<<<idivup(N, 256), 256>>>(h3, Wf, bf, (float*)d_out, N);
}